// round 1
// baseline (speedup 1.0000x reference)
#include <cuda_runtime.h>
#include <cuda_bf16.h>

// Problem constants
#define NN       8192
#define IN_DIM   256
#define NHEAD    4
#define HDIM     64
#define COLS     256   // NHEAD*HDIM

// f32x2 packed helpers (sm_100+)
#define FMA2(d, a, b, c) \
    asm("fma.rn.f32x2 %0, %1, %2, %3;" : "=l"(d) : "l"(a), "l"(b), "l"(c))
#define PACK2(out, lo, hi) \
    asm("mov.b64 %0, {%1, %2};" : "=l"(out) : "f"(lo), "f"(hi))
#define UNPACK2(lo, hi, in) \
    asm("mov.b64 {%0, %1}, %2;" : "=f"(lo), "=f"(hi) : "l"(in))

// Scratch (device globals: allowed, no allocation)
__device__ float  g_Wht[NN * COLS];     // Wh transposed-interleaved: [n][h*64+d]  (8 MB)
__device__ float4 g_S1[NN * NHEAD];     // per (i,h): {s1, exp(s1), exp(0.2 s1), 0}
__device__ float4 g_EFS[NN * NHEAD];    // per (j,h): {s2, exp(s2), exp(0.2 s2), 0}

// ---------------------------------------------------------------------------
// Kernel 1: Wh[n][c] = sum_k h[n][k] * W[h(c)][k][d(c)]
// block: 256 threads (one output column each), 16 rows per block
// ---------------------------------------------------------------------------
__global__ __launch_bounds__(256) void k_gemm(const float* __restrict__ hmat,
                                              const float* __restrict__ W)
{
    __shared__ __align__(16) float hsT[IN_DIM][18];  // [k][row], pad 18
    const int n0 = blockIdx.x * 16;
    const int t  = threadIdx.x;

    // stage h rows transposed: 16 rows x 256 k = 1024 float4
    for (int q = t; q < 1024; q += 256) {
        int row = q >> 6, kq = q & 63;
        float4 v = *(const float4*)(hmat + (n0 + row) * IN_DIM + kq * 4);
        hsT[kq * 4 + 0][row] = v.x;
        hsT[kq * 4 + 1][row] = v.y;
        hsT[kq * 4 + 2][row] = v.z;
        hsT[kq * 4 + 3][row] = v.w;
    }
    __syncthreads();

    const int c = t;
    const int head = c >> 6, d = c & 63;
    const float* Wp = W + head * (IN_DIM * HDIM) + d;

    unsigned long long acc[8];
#pragma unroll
    for (int rp = 0; rp < 8; rp++) acc[rp] = 0ull;

#pragma unroll 4
    for (int k = 0; k < IN_DIM; k++) {
        float wv = Wp[k * HDIM];
        unsigned long long ws;
        PACK2(ws, wv, wv);
#pragma unroll
        for (int rp = 0; rp < 8; rp++) {
            unsigned long long hv = *(const unsigned long long*)&hsT[k][rp * 2];
            FMA2(acc[rp], hv, ws, acc[rp]);
        }
    }

#pragma unroll
    for (int rp = 0; rp < 8; rp++) {
        float lo, hi;
        UNPACK2(lo, hi, acc[rp]);
        g_Wht[(n0 + rp * 2 + 0) * COLS + c] = lo;
        g_Wht[(n0 + rp * 2 + 1) * COLS + c] = hi;
    }
}

// ---------------------------------------------------------------------------
// Kernel 1b: per (n,h): s1 = Wh . a1, s2 = Wh . a2, then exp() precompute.
// One warp per (n,h). 256 thr/block = 8 warps; grid 4096 blocks (exact).
// ---------------------------------------------------------------------------
__global__ __launch_bounds__(256) void k_scores(const float* __restrict__ a)
{
    const int gw   = (blockIdx.x * blockDim.x + threadIdx.x) >> 5;
    const int lane = threadIdx.x & 31;
    const int n = gw >> 2, head = gw & 3;

    float2 wv = *(const float2*)(g_Wht + n * COLS + head * HDIM + lane * 2);
    float a1x = a[lane * 2],      a1y = a[lane * 2 + 1];
    float a2x = a[64 + lane * 2], a2y = a[64 + lane * 2 + 1];
    float p1 = wv.x * a1x + wv.y * a1y;
    float p2 = wv.x * a2x + wv.y * a2y;
#pragma unroll
    for (int off = 16; off > 0; off >>= 1) {
        p1 += __shfl_xor_sync(0xFFFFFFFFu, p1, off);
        p2 += __shfl_xor_sync(0xFFFFFFFFu, p2, off);
    }
    if (lane == 0) {
        float4 v1 = make_float4(p1, expf(p1), expf(0.2f * p1), 0.0f);
        float4 v2 = make_float4(p2, expf(p2), expf(0.2f * p2), 0.0f);
        g_S1 [n * NHEAD + head] = v1;
        g_EFS[n * NHEAD + head] = v2;
    }
}

// ---------------------------------------------------------------------------
// Kernel 2: masked-softmax-weighted aggregation (the heavy one).
// Block = 256 thr = 64 rows x 4 heads. Each thread accumulates 64 d-values
// (32 f32x2 regs) for its (row, head). j processed in TJ=32 chunks via smem.
// ---------------------------------------------------------------------------
#define TI 64
#define TJ 32

__global__ __launch_bounds__(256) void k_attn(const int* __restrict__ adj,
                                              float* __restrict__ out)
{
    __shared__ __align__(16) float  wh_s[TJ * 272];   // [jj][h][68 pad]
    __shared__ __align__(16) float  adjf_s[TI * 36];  // [i][36 pad]
    __shared__ __align__(16) float4 efs_s[TJ * NHEAD];

    const int t   = threadIdx.x;
    const int i_l = t >> 2;
    const int hh  = t & 3;
    const int i0  = blockIdx.x * TI;
    const int i   = i0 + i_l;

    const float4 s1v = g_S1[i * NHEAD + hh];
    const float s1 = s1v.x, E1 = s1v.y, F1 = s1v.z;

    unsigned long long acc[32];
#pragma unroll
    for (int q = 0; q < 32; q++) acc[q] = 0ull;
    float denom = 0.0f;

    for (int j0 = 0; j0 < NN; j0 += TJ) {
        __syncthreads();
        // stage Wh chunk: TJ rows x 64 float4 (pad each head to 68 floats)
#pragma unroll
        for (int q = t; q < TJ * 64; q += 256) {
            int jj = q >> 6, r = q & 63;
            float4 v = *(const float4*)(g_Wht + (j0 + jj) * COLS + r * 4);
            int h2 = r >> 4, d4 = r & 15;
            *(float4*)(wh_s + jj * 272 + h2 * 68 + d4 * 4) = v;
        }
        // stage adj chunk as float 0/1: TI x TJ ints
#pragma unroll
        for (int q = t; q < TI * (TJ / 4); q += 256) {
            int ii = q >> 3, p = q & 7;
            int4 av = *(const int4*)(adj + (long long)(i0 + ii) * NN + j0 + p * 4);
            float4 f = make_float4((float)av.x, (float)av.y, (float)av.z, (float)av.w);
            *(float4*)(adjf_s + ii * 36 + p * 4) = f;
        }
        // stage {s2,E2,F2}: TJ*4 float4, contiguous
        if (t < TJ * NHEAD) efs_s[t] = g_EFS[j0 * NHEAD + t];
        __syncthreads();

#pragma unroll 2
        for (int jj = 0; jj < TJ; jj++) {
            float4 e    = efs_s[jj * NHEAD + hh];
            float  adjf = adjf_s[i_l * 36 + jj];
            float  x    = s1 + e.x;
            float  base = (x > 0.0f) ? (E1 * e.y) : (F1 * e.z);
            float  w    = base * adjf;
            denom += w;
            unsigned long long w2;
            PACK2(w2, w, w);
            const ulonglong2* wp = (const ulonglong2*)(wh_s + jj * 272 + hh * 68);
#pragma unroll
            for (int q = 0; q < 16; q++) {
                ulonglong2 wv = wp[q];
                FMA2(acc[2 * q + 0], wv.x, w2, acc[2 * q + 0]);
                FMA2(acc[2 * q + 1], wv.y, w2, acc[2 * q + 1]);
            }
        }
    }

    const float inv = 1.0f / denom;
    float* op = out + (long long)i * COLS + hh * HDIM;
#pragma unroll
    for (int q = 0; q < 16; q++) {
        float x0, x1, x2, x3;
        UNPACK2(x0, x1, acc[2 * q + 0]);
        UNPACK2(x2, x3, acc[2 * q + 1]);
        float4 v = make_float4(x0 * inv, x1 * inv, x2 * inv, x3 * inv);
        *(float4*)(op + q * 4) = v;
    }
}

// ---------------------------------------------------------------------------
extern "C" void kernel_launch(void* const* d_in, const int* in_sizes, int n_in,
                              void* d_out, int out_size)
{
    const float* hmat = (const float*)d_in[0];   // [8192, 256] f32
    const int*   adj  = (const int*)  d_in[1];   // [8192, 8192] i32
    const float* W    = (const float*)d_in[2];   // [4, 256, 64] f32
    const float* a    = (const float*)d_in[3];   // [128, 1] f32
    float* out = (float*)d_out;                  // [8192, 256] f32

    k_gemm  <<<NN / 16, 256>>>(hmat, W);
    k_scores<<<(NN * NHEAD) / 8, 256>>>(a);
    k_attn  <<<NN / TI, 256>>>(adj, out);
}

// round 2
// speedup vs baseline: 2.3363x; 2.3363x over previous
#include <cuda_runtime.h>
#include <cuda_bf16.h>

// Problem constants
#define NN       8192
#define IN_DIM   256
#define NHEAD    4
#define HDIM     64
#define COLS     256   // NHEAD*HDIM

// attention-kernel tiling
#define TI   128        // rows per block
#define TJ   32         // j-chunk
#define JS   16         // j-splits (blocks per row-tile)
#define JCH  (NN / JS / TJ)   // chunks per block = 16

// smem layout (floats)
#define WH_JSTRIDE 320              // 16 colgroups * (16+4 pad)
#define WS_HSTRIDE 4104             // 32*128 + 8 pad
#define SM_WH   0
#define SM_W    (TJ * WH_JSTRIDE)                  // 10240
#define SM_EFS  (SM_W + NHEAD * WS_HSTRIDE)        // 26656
#define SMEM_FLOATS (SM_EFS + TJ * NHEAD * 4)      // + 512
#define SMEM_BYTES  (SMEM_FLOATS * 4)              // 108672 B

// f32x2 packed helpers (sm_100+)
#define FMA2(d, a, b, c) \
    asm("fma.rn.f32x2 %0, %1, %2, %3;" : "=l"(d) : "l"(a), "l"(b), "l"(c))
#define ADD2(d, a, b) \
    asm("add.rn.f32x2 %0, %1, %2;" : "=l"(d) : "l"(a), "l"(b))
#define PACK2(out, lo, hi) \
    asm("mov.b64 %0, {%1, %2};" : "=l"(out) : "f"(lo), "f"(hi))
#define UNPACK2(lo, hi, in) \
    asm("mov.b64 {%0, %1}, %2;" : "=f"(lo), "=f"(hi) : "l"(in))
#define BCAST2(d0, d1, src) { float _lo, _hi; UNPACK2(_lo, _hi, src); \
                              PACK2(d0, _lo, _lo); PACK2(d1, _hi, _hi); }

// Scratch (device globals: allowed, no allocation)
__device__ float  g_Wht[NN * COLS];           // Wh: [n][h*64+d]   (8 MB)
__device__ float4 g_S1[NN * NHEAD];           // per (i,h): {s1, exp(s1), exp(0.2 s1), 0}
__device__ float4 g_EFS[NN * NHEAD];          // per (j,h): {s2, exp(s2), exp(0.2 s2), 0}
__device__ float  g_outP[(size_t)JS * NN * COLS];   // partial sums (128 MB)
__device__ float  g_denP[(size_t)JS * NN * NHEAD];  // partial denominators (2 MB)

// ---------------------------------------------------------------------------
// Kernel 1: Wh[n][c] = sum_k h[n][k] * W[h(c)][k][d(c)]
// ---------------------------------------------------------------------------
__global__ __launch_bounds__(256) void k_gemm(const float* __restrict__ hmat,
                                              const float* __restrict__ W)
{
    __shared__ __align__(16) float hsT[IN_DIM][18];
    const int n0 = blockIdx.x * 16;
    const int t  = threadIdx.x;

    for (int q = t; q < 1024; q += 256) {
        int row = q >> 6, kq = q & 63;
        float4 v = *(const float4*)(hmat + (n0 + row) * IN_DIM + kq * 4);
        hsT[kq * 4 + 0][row] = v.x;
        hsT[kq * 4 + 1][row] = v.y;
        hsT[kq * 4 + 2][row] = v.z;
        hsT[kq * 4 + 3][row] = v.w;
    }
    __syncthreads();

    const int c = t;
    const int head = c >> 6, d = c & 63;
    const float* Wp = W + head * (IN_DIM * HDIM) + d;

    unsigned long long acc[8];
#pragma unroll
    for (int rp = 0; rp < 8; rp++) acc[rp] = 0ull;

#pragma unroll 4
    for (int k = 0; k < IN_DIM; k++) {
        float wv = Wp[k * HDIM];
        unsigned long long ws;
        PACK2(ws, wv, wv);
#pragma unroll
        for (int rp = 0; rp < 8; rp++) {
            unsigned long long hv = *(const unsigned long long*)&hsT[k][rp * 2];
            FMA2(acc[rp], hv, ws, acc[rp]);
        }
    }

#pragma unroll
    for (int rp = 0; rp < 8; rp++) {
        float lo, hi;
        UNPACK2(lo, hi, acc[rp]);
        g_Wht[(n0 + rp * 2 + 0) * COLS + c] = lo;
        g_Wht[(n0 + rp * 2 + 1) * COLS + c] = hi;
    }
}

// ---------------------------------------------------------------------------
// Kernel 1b: per (n,h): s = Wh . a ; precompute {s, exp(s), exp(0.2 s)}
// ---------------------------------------------------------------------------
__global__ __launch_bounds__(256) void k_scores(const float* __restrict__ a)
{
    const int gw   = (blockIdx.x * blockDim.x + threadIdx.x) >> 5;
    const int lane = threadIdx.x & 31;
    const int n = gw >> 2, head = gw & 3;

    float2 wv = *(const float2*)(g_Wht + n * COLS + head * HDIM + lane * 2);
    float a1x = a[lane * 2],      a1y = a[lane * 2 + 1];
    float a2x = a[64 + lane * 2], a2y = a[64 + lane * 2 + 1];
    float p1 = wv.x * a1x + wv.y * a1y;
    float p2 = wv.x * a2x + wv.y * a2y;
#pragma unroll
    for (int off = 16; off > 0; off >>= 1) {
        p1 += __shfl_xor_sync(0xFFFFFFFFu, p1, off);
        p2 += __shfl_xor_sync(0xFFFFFFFFu, p2, off);
    }
    if (lane == 0) {
        g_S1 [n * NHEAD + head] = make_float4(p1, expf(p1), expf(0.2f * p1), 0.0f);
        g_EFS[n * NHEAD + head] = make_float4(p2, expf(p2), expf(0.2f * p2), 0.0f);
    }
}

// ---------------------------------------------------------------------------
// Kernel 2: masked-softmax-weighted aggregation, register-tiled 8x16.
// Block = 256 thr, covers TI=128 rows x 256 cols, j-range NN/JS.
// ---------------------------------------------------------------------------
__global__ __launch_bounds__(256, 1) void k_attn(const int* __restrict__ adj)
{
    extern __shared__ __align__(16) float sm[];
    float*  wh_s  = sm + SM_WH;
    float*  w_s   = sm + SM_W;
    float4* efs_s = (float4*)(sm + SM_EFS);

    const int t  = threadIdx.x;
    const int bx = blockIdx.x;
    const int js    = bx & (JS - 1);
    const int itile = bx >> 4;           // JS = 16
    const int i0     = itile * TI;
    const int j0base = js * (NN / JS);

    // main-loop coords: 16 colgroups (16 cols each) x 16 igroups (8 rows each)
    const int cg = t & 15;
    const int ig = t >> 4;
    const int headM = cg >> 2;
    const int iA = ig * 8;

    // weight-phase coords: 128 i-lanes x 2 jj-halves
    const int iw = t & 127;
    const int jh = t >> 7;

    // per-row score state for the weight phase (row i0+iw, all heads)
    float s1h[4], E1h[4], F1h[4];
    {
        const float4* S1p = g_S1 + (i0 + iw) * NHEAD;
#pragma unroll
        for (int h = 0; h < 4; h++) {
            float4 v = S1p[h];
            s1h[h] = v.x; E1h[h] = v.y; F1h[h] = v.z;
        }
    }

    unsigned long long acc[64];
#pragma unroll
    for (int q = 0; q < 64; q++) acc[q] = 0ull;
    unsigned long long den2[4] = {0ull, 0ull, 0ull, 0ull};

    for (int ch = 0; ch < JCH; ch++) {
        const int j0 = j0base + ch * TJ;

        // issue adj loads early (latency overlaps the staging below)
        int4 aj[4];
        {
            const int4* ap = (const int4*)(adj + (size_t)(i0 + iw) * NN + j0 + jh * 16);
#pragma unroll
            for (int q = 0; q < 4; q++) aj[q] = ap[q];
        }

        __syncthreads();   // previous main loop done with smem

        // stage Wh chunk: TJ x 256 floats -> padded colgroup layout
#pragma unroll
        for (int q = 0; q < 8; q++) {
            int idx = t + q * 256;           // 0..2047 float4s
            int jj  = idx >> 6;
            int c4  = idx & 63;
            float4 v = *(const float4*)(g_Wht + (j0 + jj) * COLS + c4 * 4);
            *(float4*)(wh_s + jj * WH_JSTRIDE + (c4 >> 2) * 20 + (c4 & 3) * 4) = v;
        }
        // stage {s2,E2,F2} for the chunk
        if (t < TJ * NHEAD) efs_s[t] = ((const float4*)g_EFS)[j0 * NHEAD + t];
        __syncthreads();

        // weight phase: w[h][jj][i] = adj * (x>0 ? E1*E2 : F1*F2)
        {
            const int* ajp = (const int*)aj;
#pragma unroll
            for (int q = 0; q < 16; q++) {
                int jj = jh * 16 + q;
                float av = __int2float_rn(ajp[q]);
#pragma unroll
                for (int h = 0; h < 4; h++) {
                    float4 e = efs_s[jj * NHEAD + h];
                    float x = s1h[h] + e.x;
                    float w = (x > 0.0f) ? (E1h[h] * e.y) : (F1h[h] * e.z);
                    w_s[h * WS_HSTRIDE + jj * TI + iw] = w * av;
                }
            }
        }
        __syncthreads();

        // main loop: rows iA..iA+7, cols cg*16..+15
        const float* whp = wh_s + cg * 20;
        const float* wpp = w_s + headM * WS_HSTRIDE + iA;
#pragma unroll 2
        for (int jj = 0; jj < TJ; jj++) {
            ulonglong2 wA = *(const ulonglong2*)(wpp + jj * TI);
            ulonglong2 wB = *(const ulonglong2*)(wpp + jj * TI + 4);
            ADD2(den2[0], den2[0], wA.x);
            ADD2(den2[1], den2[1], wA.y);
            ADD2(den2[2], den2[2], wB.x);
            ADD2(den2[3], den2[3], wB.y);

            unsigned long long w2[8];
            BCAST2(w2[0], w2[1], wA.x);
            BCAST2(w2[2], w2[3], wA.y);
            BCAST2(w2[4], w2[5], wB.x);
            BCAST2(w2[6], w2[7], wB.y);

            const float* wh = whp + jj * WH_JSTRIDE;
            ulonglong2 h0 = *(const ulonglong2*)(wh);
            ulonglong2 h1 = *(const ulonglong2*)(wh + 4);
            ulonglong2 h2 = *(const ulonglong2*)(wh + 8);
            ulonglong2 h3 = *(const ulonglong2*)(wh + 12);
            unsigned long long hv[8] = {h0.x, h0.y, h1.x, h1.y, h2.x, h2.y, h3.x, h3.y};

#pragma unroll
            for (int r = 0; r < 8; r++)
#pragma unroll
                for (int q = 0; q < 8; q++)
                    FMA2(acc[r * 8 + q], hv[q], w2[r], acc[r * 8 + q]);
        }
    }

    // epilogue: write partial denominators + partial sums
    if ((cg & 3) == 0) {
        float d[8];
        UNPACK2(d[0], d[1], den2[0]);
        UNPACK2(d[2], d[3], den2[1]);
        UNPACK2(d[4], d[5], den2[2]);
        UNPACK2(d[6], d[7], den2[3]);
#pragma unroll
        for (int r = 0; r < 8; r++)
            g_denP[((size_t)js * NN + i0 + iA + r) * NHEAD + headM] = d[r];
    }
    float* op = g_outP + ((size_t)js * NN + i0 + iA) * COLS + cg * 16;
#pragma unroll
    for (int r = 0; r < 8; r++) {
#pragma unroll
        for (int q = 0; q < 4; q++) {
            float x0, x1, x2, x3;
            UNPACK2(x0, x1, acc[r * 8 + q * 2 + 0]);
            UNPACK2(x2, x3, acc[r * 8 + q * 2 + 1]);
            *(float4*)(op + r * COLS + q * 4) = make_float4(x0, x1, x2, x3);
        }
    }
}

// ---------------------------------------------------------------------------
// Kernel 3: combine j-split partials and divide by full denominator.
// ---------------------------------------------------------------------------
__global__ __launch_bounds__(256) void k_comb(float* __restrict__ out)
{
    const int idx = blockIdx.x * 256 + threadIdx.x;   // float4 index over NN*64
    const int i  = idx >> 6;
    const int c4 = idx & 63;
    const int h  = c4 >> 4;

    float4 s = make_float4(0.f, 0.f, 0.f, 0.f);
    float d = 0.f;
#pragma unroll
    for (int js = 0; js < JS; js++) {
        float4 p = ((const float4*)g_outP)[((size_t)js * NN + i) * 64 + c4];
        s.x += p.x; s.y += p.y; s.z += p.z; s.w += p.w;
        d += g_denP[((size_t)js * NN + i) * NHEAD + h];
    }
    float inv = 1.0f / d;
    ((float4*)out)[idx] = make_float4(s.x * inv, s.y * inv, s.z * inv, s.w * inv);
}

// ---------------------------------------------------------------------------
extern "C" void kernel_launch(void* const* d_in, const int* in_sizes, int n_in,
                              void* d_out, int out_size)
{
    const float* hmat = (const float*)d_in[0];   // [8192, 256] f32
    const int*   adj  = (const int*)  d_in[1];   // [8192, 8192] i32
    const float* W    = (const float*)d_in[2];   // [4, 256, 64] f32
    const float* a    = (const float*)d_in[3];   // [128, 1] f32
    float* out = (float*)d_out;                  // [8192, 256] f32

    cudaFuncSetAttribute(k_attn, cudaFuncAttributeMaxDynamicSharedMemorySize, SMEM_BYTES);

    k_gemm  <<<NN / 16, 256>>>(hmat, W);
    k_scores<<<(NN * NHEAD) / 8, 256>>>(a);
    k_attn  <<<(NN / TI) * JS, 256, SMEM_BYTES>>>(adj);
    k_comb  <<<(NN * 64) / 256, 256>>>(out);
}

// round 4
// speedup vs baseline: 3.8570x; 1.6509x over previous
#include <cuda_runtime.h>
#include <cuda_fp16.h>
#include <cstdint>

// Problem constants
#define NN       8192
#define IN_DIM   256
#define NHEAD    4
#define HDIM     64
#define COLS     256   // NHEAD*HDIM

// attention tiling
#define TI   128                   // rows per block
#define TJ   64                    // j per chunk (K)
#define JS   16                    // j-splits
#define JCH  ((NN / JS) / TJ)      // 8 chunks per block

// smem byte offsets (from 1024-aligned base)
#define OFF_B     0u               // 2 bufs x 32768 (4 heads x 64 c-rows x 128B fp16)
#define OFF_EFS   65536u           // 2 bufs x 4096  (64 j x 4 h x float4)
#define OFF_S1    73728u           // 8192 (128 i x 4 h x float4)
#define SMEM_REQ  (81920u + 1024u)

#define SMEM_SWZ(off) ((off) ^ (((off) >> 3) & 0x70u))

// ---------------- PTX helpers ----------------
__device__ __forceinline__ uint32_t smem_u32(const void* p) {
    uint32_t a;
    asm("{ .reg .u64 t; cvta.to.shared.u64 t, %1; cvt.u32.u64 %0, t; }" : "=r"(a) : "l"(p));
    return a;
}
#define PACK2(out, lo, hi) \
    asm("mov.b64 %0, {%1, %2};" : "=l"(out) : "f"(lo), "f"(hi))
#define UNPACK2(lo, hi, in) \
    asm("mov.b64 {%0, %1}, %2;" : "=f"(lo), "=f"(hi) : "l"(in))
#define FMA2(d, a, b, c) \
    asm("fma.rn.f32x2 %0, %1, %2, %3;" : "=l"(d) : "l"(a), "l"(b), "l"(c))
// pack two f32 -> f16x2 (lo in low half)
#define CVT_F16X2(r, lo, hi) \
    asm("cvt.rn.f16x2.f32 %0, %1, %2;" : "=r"(r) : "f"(hi), "f"(lo))

#define CP_ASYNC16(dst, src) \
    asm volatile("cp.async.cg.shared.global [%0], [%1], 16;" :: "r"(dst), "l"(src))
#define CP_COMMIT() asm volatile("cp.async.commit_group;" ::: "memory")
#define CP_WAIT(n)  asm volatile("cp.async.wait_group %0;" :: "n"(n) : "memory")

#define LDSM4(r, addr) \
    asm volatile("ldmatrix.sync.aligned.m8n8.x4.shared.b16 {%0,%1,%2,%3}, [%4];" \
        : "=r"((r)[0]), "=r"((r)[1]), "=r"((r)[2]), "=r"((r)[3]) : "r"(addr))

#define MMA16816(d, a0, a1, a2, a3, b0, b1) \
    asm volatile("mma.sync.aligned.m16n8k16.row.col.f32.f16.f16.f32 " \
        "{%0,%1,%2,%3}, {%4,%5,%6,%7}, {%8,%9}, {%0,%1,%2,%3};" \
        : "+f"((d)[0]), "+f"((d)[1]), "+f"((d)[2]), "+f"((d)[3]) \
        : "r"(a0), "r"(a1), "r"(a2), "r"(a3), "r"(b0), "r"(b1))

// ---------------- scratch globals ----------------
__device__ float   g_Wht[NN * COLS];            // Wh fp32 [n][c] (for scores)
__device__ __half  g_WTf16[COLS * NN];          // Wh^T fp16 [c][j]  (4 MB)
__device__ float4  g_S1[NN * NHEAD];            // {s1, e^s1, e^{.2 s1}, 0}
__device__ float4  g_EFS[NN * NHEAD];           // {s2, e^s2, e^{.2 s2}, 0}
__device__ float   g_outP[(size_t)JS * NN * COLS];
__device__ float   g_denP[(size_t)JS * NN * NHEAD];

// ---------------------------------------------------------------------------
// Kernel 1: Wh = h @ W ; also emit fp16 Wh^T plane.
// ---------------------------------------------------------------------------
__global__ __launch_bounds__(256) void k_gemm(const float* __restrict__ hmat,
                                              const float* __restrict__ W)
{
    __shared__ __align__(16) float hsT[IN_DIM][18];
    const int n0 = blockIdx.x * 16;
    const int t  = threadIdx.x;

    for (int q = t; q < 1024; q += 256) {
        int row = q >> 6, kq = q & 63;
        float4 v = *(const float4*)(hmat + (n0 + row) * IN_DIM + kq * 4);
        hsT[kq * 4 + 0][row] = v.x;
        hsT[kq * 4 + 1][row] = v.y;
        hsT[kq * 4 + 2][row] = v.z;
        hsT[kq * 4 + 3][row] = v.w;
    }
    __syncthreads();

    const int c = t;
    const int head = c >> 6, d = c & 63;
    const float* Wp = W + head * (IN_DIM * HDIM) + d;

    unsigned long long acc[8];
#pragma unroll
    for (int rp = 0; rp < 8; rp++) acc[rp] = 0ull;

#pragma unroll 4
    for (int k = 0; k < IN_DIM; k++) {
        float wv = Wp[k * HDIM];
        unsigned long long ws;
        PACK2(ws, wv, wv);
#pragma unroll
        for (int rp = 0; rp < 8; rp++) {
            unsigned long long hv = *(const unsigned long long*)&hsT[k][rp * 2];
            FMA2(acc[rp], hv, ws, acc[rp]);
        }
    }

    float val[16];
#pragma unroll
    for (int rp = 0; rp < 8; rp++) {
        UNPACK2(val[2 * rp], val[2 * rp + 1], acc[rp]);
        g_Wht[(n0 + 2 * rp + 0) * COLS + c] = val[2 * rp];
        g_Wht[(n0 + 2 * rp + 1) * COLS + c] = val[2 * rp + 1];
    }
    uint32_t hp[8];
#pragma unroll
    for (int q = 0; q < 8; q++) CVT_F16X2(hp[q], val[2 * q], val[2 * q + 1]);
    uint4* pd = (uint4*)(g_WTf16 + (size_t)c * NN + n0);
    pd[0] = make_uint4(hp[0], hp[1], hp[2], hp[3]);
    pd[1] = make_uint4(hp[4], hp[5], hp[6], hp[7]);
}

// ---------------------------------------------------------------------------
// Kernel 1b: scores + exp precompute
// ---------------------------------------------------------------------------
__global__ __launch_bounds__(256) void k_scores(const float* __restrict__ a)
{
    const int gw   = (blockIdx.x * blockDim.x + threadIdx.x) >> 5;
    const int lane = threadIdx.x & 31;
    const int n = gw >> 2, head = gw & 3;

    float2 wv = *(const float2*)(g_Wht + n * COLS + head * HDIM + lane * 2);
    float a1x = a[lane * 2],      a1y = a[lane * 2 + 1];
    float a2x = a[64 + lane * 2], a2y = a[64 + lane * 2 + 1];
    float p1 = wv.x * a1x + wv.y * a1y;
    float p2 = wv.x * a2x + wv.y * a2y;
#pragma unroll
    for (int off = 16; off > 0; off >>= 1) {
        p1 += __shfl_xor_sync(0xFFFFFFFFu, p1, off);
        p2 += __shfl_xor_sync(0xFFFFFFFFu, p2, off);
    }
    if (lane == 0) {
        g_S1 [n * NHEAD + head] = make_float4(p1, expf(p1), expf(0.2f * p1), 0.0f);
        g_EFS[n * NHEAD + head] = make_float4(p2, expf(p2), expf(0.2f * p2), 0.0f);
    }
}

// ---------------------------------------------------------------------------
// Kernel 2: HMMA attention aggregation. grid = (NN/TI)*JS = 1024, 256 thr.
// Warp w owns rows i0 + w*16 .. +15; computes all 4 heads x 64 cols.
// ---------------------------------------------------------------------------
__global__ __launch_bounds__(256, 1) void k_attn(const int* __restrict__ adj)
{
    extern __shared__ __align__(16) char dsm[];
    const uint32_t sb = smem_u32(dsm);
    const uint32_t ab = (sb + 1023u) & ~1023u;
    char* abp = dsm + (ab - sb);

    const int t    = threadIdx.x;
    const int wid  = t >> 5;
    const int lane = t & 31;
    const int g    = lane >> 2;
    const int tg   = lane & 3;
    const int bx = blockIdx.x;
    const int js    = bx & (JS - 1);
    const int itile = bx >> 4;
    const int i0     = itile * TI;
    const int j0base = js * (NN / JS);

    const int ilA = wid * 16 + g;          // local row A
    const int iA  = i0 + ilA;              // global row A (B = +8)

    // stage S1 once (visible after first barrier)
    for (int idx = t; idx < TI * NHEAD; idx += 256)
        *(float4*)(abp + OFF_S1 + idx * 16) = g_S1[i0 * NHEAD + idx];

    // ---- cp.async staging helper (inlined via lambda-like macro) ----
    auto stage = [&](int buf, int j0) {
        // B: 256 c-rows x 64 j fp16; 16B granules, swizzled
#pragma unroll
        for (int v = 0; v < 8; v++) {
            int idx = v * 256 + t;
            int row = idx >> 3, u = idx & 7;
            const __half* src = g_WTf16 + (size_t)row * NN + j0 + u * 8;
            uint32_t dst = ab + OFF_B + buf * 32768 + SMEM_SWZ((uint32_t)(row * 128 + u * 16));
            CP_ASYNC16(dst, src);
        }
        // EFS: 64 j x 4 h float4
        {
            const float4* src = g_EFS + j0 * NHEAD + t;
            uint32_t dst = ab + OFF_EFS + buf * 4096 + t * 16;
            CP_ASYNC16(dst, src);
        }
    };

    stage(0, j0base);
    CP_COMMIT();

    float acc[NHEAD][8][4];
#pragma unroll
    for (int h = 0; h < NHEAD; h++)
#pragma unroll
        for (int nt = 0; nt < 8; nt++)
#pragma unroll
            for (int q = 0; q < 4; q++) acc[h][nt][q] = 0.0f;
    float den[2][NHEAD];
#pragma unroll
    for (int r = 0; r < 2; r++)
#pragma unroll
        for (int h = 0; h < NHEAD; h++) den[r][h] = 0.0f;

    for (int ch = 0; ch < JCH; ch++) {
        const int buf = ch & 1;
        const int j0  = j0base + ch * TJ;

        if (ch + 1 < JCH) { stage(buf ^ 1, j0 + TJ); CP_COMMIT(); }

        // adj bitmasks for this chunk (global loads overlap cp.async wait)
        uint32_t mA = 0, mB = 0;
        {
            const int* ap = adj + (size_t)iA * NN + j0 + tg * 2;
#pragma unroll
            for (int s = 0; s < 4; s++) {
                int2 a0 = *(const int2*)(ap + s * 16);
                int2 a1 = *(const int2*)(ap + s * 16 + 8);
                int2 b0 = *(const int2*)(ap + (size_t)8 * NN + s * 16);
                int2 b1 = *(const int2*)(ap + (size_t)8 * NN + s * 16 + 8);
                mA |= (uint32_t)(a0.x & 1) << (s * 4) | (uint32_t)(a0.y & 1) << (s * 4 + 1)
                    | (uint32_t)(a1.x & 1) << (s * 4 + 2) | (uint32_t)(a1.y & 1) << (s * 4 + 3);
                mB |= (uint32_t)(b0.x & 1) << (s * 4) | (uint32_t)(b0.y & 1) << (s * 4 + 1)
                    | (uint32_t)(b1.x & 1) << (s * 4 + 2) | (uint32_t)(b1.y & 1) << (s * 4 + 3);
            }
        }

        if (ch + 1 < JCH) CP_WAIT(1); else CP_WAIT(0);
        __syncthreads();

        const float4* efs = (const float4*)(abp + OFF_EFS + buf * 4096);
        const uint32_t Bb = ab + OFF_B + buf * 32768;

        // ldmatrix per-lane address pieces
        const int r_c = lane & 7;
        const int jo  = ((lane >> 3) & 3) * 8;   // 0,8,16,24

#pragma unroll
        for (int h = 0; h < NHEAD; h++) {
            float4 sva = *(const float4*)(abp + OFF_S1 + ((ilA) * 4 + h) * 16);
            float4 svb = *(const float4*)(abp + OFF_S1 + ((ilA + 8) * 4 + h) * 16);

#pragma unroll
            for (int sp = 0; sp < 2; sp++) {
                // B fragments: 8 n-tiles x (2 ksteps x 2 regs)
                uint32_t bfr[8][4];
#pragma unroll
                for (int nt = 0; nt < 8; nt++) {
                    uint32_t addr = Bb + (uint32_t)(h * 8192)
                        + SMEM_SWZ((uint32_t)((nt * 8 + r_c) * 128 + (sp * 32 + jo) * 2));
                    LDSM4(bfr[nt], addr);
                }
                // A fragments (hi/lo) for 2 ksteps
                uint32_t ahi[2][4], alo[2][4];
#pragma unroll
                for (int k2 = 0; k2 < 2; k2++) {
                    const int s  = sp * 2 + k2;
                    const int jj = s * 16 + tg * 2;
                    float4 e0 = efs[(jj)     * 4 + h];
                    float4 e1 = efs[(jj + 1) * 4 + h];
                    float4 e2 = efs[(jj + 8) * 4 + h];
                    float4 e3 = efs[(jj + 9) * 4 + h];

                    float wA0, wA1, wA2, wA3, wB0, wB1, wB2, wB3;
                    {
                        float x;
                        x = sva.x + e0.x; wA0 = ((mA >> (s*4+0)) & 1) ? (x > 0.f ? sva.y*e0.y : sva.z*e0.z) : 0.f;
                        x = sva.x + e1.x; wA1 = ((mA >> (s*4+1)) & 1) ? (x > 0.f ? sva.y*e1.y : sva.z*e1.z) : 0.f;
                        x = sva.x + e2.x; wA2 = ((mA >> (s*4+2)) & 1) ? (x > 0.f ? sva.y*e2.y : sva.z*e2.z) : 0.f;
                        x = sva.x + e3.x; wA3 = ((mA >> (s*4+3)) & 1) ? (x > 0.f ? sva.y*e3.y : sva.z*e3.z) : 0.f;
                        x = svb.x + e0.x; wB0 = ((mB >> (s*4+0)) & 1) ? (x > 0.f ? svb.y*e0.y : svb.z*e0.z) : 0.f;
                        x = svb.x + e1.x; wB1 = ((mB >> (s*4+1)) & 1) ? (x > 0.f ? svb.y*e1.y : svb.z*e1.z) : 0.f;
                        x = svb.x + e2.x; wB2 = ((mB >> (s*4+2)) & 1) ? (x > 0.f ? svb.y*e2.y : svb.z*e2.z) : 0.f;
                        x = svb.x + e3.x; wB3 = ((mB >> (s*4+3)) & 1) ? (x > 0.f ? svb.y*e3.y : svb.z*e3.z) : 0.f;
                    }
                    den[0][h] += (wA0 + wA1) + (wA2 + wA3);
                    den[1][h] += (wB0 + wB1) + (wB2 + wB3);

                    CVT_F16X2(ahi[k2][0], wA0, wA1);
                    CVT_F16X2(ahi[k2][1], wB0, wB1);
                    CVT_F16X2(ahi[k2][2], wA2, wA3);
                    CVT_F16X2(ahi[k2][3], wB2, wB3);
#pragma unroll
                    for (int q = 0; q < 4; q++) {
                        __half2 hh = *(__half2*)&ahi[k2][q];
                        float2 hf = __half22float2(hh);
                        float u0 = (q == 0 ? wA0 : q == 1 ? wB0 : q == 2 ? wA2 : wB2) - hf.x;
                        float u1 = (q == 0 ? wA1 : q == 1 ? wB1 : q == 2 ? wA3 : wB3) - hf.y;
                        CVT_F16X2(alo[k2][q], u0, u1);
                    }
                }
                // MMAs
#pragma unroll
                for (int nt = 0; nt < 8; nt++) {
#pragma unroll
                    for (int k2 = 0; k2 < 2; k2++) {
                        MMA16816(acc[h][nt], ahi[k2][0], ahi[k2][1], ahi[k2][2], ahi[k2][3],
                                 bfr[nt][k2 * 2], bfr[nt][k2 * 2 + 1]);
                        MMA16816(acc[h][nt], alo[k2][0], alo[k2][1], alo[k2][2], alo[k2][3],
                                 bfr[nt][k2 * 2], bfr[nt][k2 * 2 + 1]);
                    }
                }
            }
        }
        __syncthreads();
    }

    // ---- epilogue ----
#pragma unroll
    for (int r = 0; r < 2; r++)
#pragma unroll
        for (int h = 0; h < NHEAD; h++) {
            den[r][h] += __shfl_xor_sync(0xFFFFFFFFu, den[r][h], 1);
            den[r][h] += __shfl_xor_sync(0xFFFFFFFFu, den[r][h], 2);
        }
    if (tg == 0) {
        *(float4*)(g_denP + ((size_t)js * NN + iA)     * NHEAD) =
            make_float4(den[0][0], den[0][1], den[0][2], den[0][3]);
        *(float4*)(g_denP + ((size_t)js * NN + iA + 8) * NHEAD) =
            make_float4(den[1][0], den[1][1], den[1][2], den[1][3]);
    }
#pragma unroll
    for (int h = 0; h < NHEAD; h++)
#pragma unroll
        for (int nt = 0; nt < 8; nt++) {
            const int c0 = h * 64 + nt * 8 + tg * 2;
            *(float2*)(g_outP + ((size_t)js * NN + iA)     * COLS + c0) =
                make_float2(acc[h][nt][0], acc[h][nt][1]);
            *(float2*)(g_outP + ((size_t)js * NN + iA + 8) * COLS + c0) =
                make_float2(acc[h][nt][2], acc[h][nt][3]);
        }
}

// ---------------------------------------------------------------------------
// Kernel 3: combine j-split partials
// ---------------------------------------------------------------------------
__global__ __launch_bounds__(256) void k_comb(float* __restrict__ out)
{
    const int idx = blockIdx.x * 256 + threadIdx.x;   // float4 index over NN*64
    const int i  = idx >> 6;
    const int c4 = idx & 63;
    const int h  = c4 >> 4;

    float4 s = make_float4(0.f, 0.f, 0.f, 0.f);
    float d = 0.f;
#pragma unroll
    for (int js = 0; js < JS; js++) {
        float4 p = ((const float4*)g_outP)[((size_t)js * NN + i) * 64 + c4];
        s.x += p.x; s.y += p.y; s.z += p.z; s.w += p.w;
        d += g_denP[((size_t)js * NN + i) * NHEAD + h];
    }
    float inv = 1.0f / d;
    ((float4*)out)[idx] = make_float4(s.x * inv, s.y * inv, s.z * inv, s.w * inv);
}

// ---------------------------------------------------------------------------
extern "C" void kernel_launch(void* const* d_in, const int* in_sizes, int n_in,
                              void* d_out, int out_size)
{
    const float* hmat = (const float*)d_in[0];   // [8192, 256] f32
    const int*   adj  = (const int*)  d_in[1];   // [8192, 8192] i32
    const float* W    = (const float*)d_in[2];   // [4, 256, 64] f32
    const float* a    = (const float*)d_in[3];   // [128, 1] f32
    float* out = (float*)d_out;                  // [8192, 256] f32

    cudaFuncSetAttribute(k_attn, cudaFuncAttributeMaxDynamicSharedMemorySize, SMEM_REQ);

    k_gemm  <<<NN / 16, 256>>>(hmat, W);
    k_scores<<<(NN * NHEAD) / 8, 256>>>(a);
    k_attn  <<<(NN / TI) * JS, 256, SMEM_REQ>>>(adj);
    k_comb  <<<(NN * 64) / 256, 256>>>(out);
}

// round 5
// speedup vs baseline: 4.1551x; 1.0773x over previous
#include <cuda_runtime.h>
#include <cuda_fp16.h>
#include <cstdint>

// Problem constants
#define NN       8192
#define IN_DIM   256
#define NHEAD    4
#define HDIM     64
#define COLS     256   // NHEAD*HDIM

// attention tiling
#define TI   128                   // rows per block
#define TJ   64                    // j per chunk (K)
#define JS   16                    // j-splits
#define JCH  ((NN / JS) / TJ)      // 8 chunks per block

// smem byte offsets (from 1024-aligned base)
#define OFF_B     0u               // 2 bufs x 32768 (4 heads x 64 c-rows x 128B fp16)
#define OFF_EFS   65536u           // 2 bufs x 4096  (64 j x 4 h x float4)
#define OFF_S1    73728u           // 8192 (128 i x 4 h x float4)
#define SMEM_REQ  (81920u + 1024u)

#define SMEM_SWZ(off) ((off) ^ (((off) >> 3) & 0x70u))

// ---------------- PTX helpers ----------------
__device__ __forceinline__ uint32_t smem_u32(const void* p) {
    uint32_t a;
    asm("{ .reg .u64 t; cvta.to.shared.u64 t, %1; cvt.u32.u64 %0, t; }" : "=r"(a) : "l"(p));
    return a;
}
#define PACK2(out, lo, hi) \
    asm("mov.b64 %0, {%1, %2};" : "=l"(out) : "f"(lo), "f"(hi))
#define UNPACK2(lo, hi, in) \
    asm("mov.b64 {%0, %1}, %2;" : "=f"(lo), "=f"(hi) : "l"(in))
#define FMA2(d, a, b, c) \
    asm("fma.rn.f32x2 %0, %1, %2, %3;" : "=l"(d) : "l"(a), "l"(b), "l"(c))
// pack two f32 -> f16x2 (lo in low half)
#define CVT_F16X2(r, lo, hi) \
    asm("cvt.rn.f16x2.f32 %0, %1, %2;" : "=r"(r) : "f"(hi), "f"(lo))

#define CP_ASYNC16(dst, src) \
    asm volatile("cp.async.cg.shared.global [%0], [%1], 16;" :: "r"(dst), "l"(src))
#define CP_COMMIT() asm volatile("cp.async.commit_group;" ::: "memory")
#define CP_WAIT(n)  asm volatile("cp.async.wait_group %0;" :: "n"(n) : "memory")

#define LDSM4(r, addr) \
    asm volatile("ldmatrix.sync.aligned.m8n8.x4.shared.b16 {%0,%1,%2,%3}, [%4];" \
        : "=r"((r)[0]), "=r"((r)[1]), "=r"((r)[2]), "=r"((r)[3]) : "r"(addr))

#define MMA16816(d, a0, a1, a2, a3, b0, b1) \
    asm volatile("mma.sync.aligned.m16n8k16.row.col.f32.f16.f16.f32 " \
        "{%0,%1,%2,%3}, {%4,%5,%6,%7}, {%8,%9}, {%0,%1,%2,%3};" \
        : "+f"((d)[0]), "+f"((d)[1]), "+f"((d)[2]), "+f"((d)[3]) \
        : "r"(a0), "r"(a1), "r"(a2), "r"(a3), "r"(b0), "r"(b1))

// ---------------- scratch globals ----------------
__device__ float   g_Wht[NN * COLS];            // Wh fp32 [n][c] (for scores)
__device__ __half  g_WTf16[COLS * NN];          // Wh^T fp16 [c][j]  (4 MB)
__device__ float4  g_S1[NN * NHEAD];            // {s1, e^s1, e^{.2 s1}, 0}
__device__ float4  g_EFS[NN * NHEAD];           // {s2, e^s2, e^{.2 s2}, 0}
__device__ float   g_outP[(size_t)JS * NN * COLS];
__device__ float   g_denP[(size_t)JS * NN * NHEAD];

// ---------------------------------------------------------------------------
// Kernel 1: Wh = h @ W ; also emit fp16 Wh^T plane.
// ---------------------------------------------------------------------------
__global__ __launch_bounds__(256) void k_gemm(const float* __restrict__ hmat,
                                              const float* __restrict__ W)
{
    __shared__ __align__(16) float hsT[IN_DIM][18];
    const int n0 = blockIdx.x * 16;
    const int t  = threadIdx.x;

    for (int q = t; q < 1024; q += 256) {
        int row = q >> 6, kq = q & 63;
        float4 v = *(const float4*)(hmat + (n0 + row) * IN_DIM + kq * 4);
        hsT[kq * 4 + 0][row] = v.x;
        hsT[kq * 4 + 1][row] = v.y;
        hsT[kq * 4 + 2][row] = v.z;
        hsT[kq * 4 + 3][row] = v.w;
    }
    __syncthreads();

    const int c = t;
    const int head = c >> 6, d = c & 63;
    const float* Wp = W + head * (IN_DIM * HDIM) + d;

    unsigned long long acc[8];
#pragma unroll
    for (int rp = 0; rp < 8; rp++) acc[rp] = 0ull;

#pragma unroll 4
    for (int k = 0; k < IN_DIM; k++) {
        float wv = Wp[k * HDIM];
        unsigned long long ws;
        PACK2(ws, wv, wv);
#pragma unroll
        for (int rp = 0; rp < 8; rp++) {
            unsigned long long hv = *(const unsigned long long*)&hsT[k][rp * 2];
            FMA2(acc[rp], hv, ws, acc[rp]);
        }
    }

    float val[16];
#pragma unroll
    for (int rp = 0; rp < 8; rp++) {
        UNPACK2(val[2 * rp], val[2 * rp + 1], acc[rp]);
        g_Wht[(n0 + 2 * rp + 0) * COLS + c] = val[2 * rp];
        g_Wht[(n0 + 2 * rp + 1) * COLS + c] = val[2 * rp + 1];
    }
    uint32_t hp[8];
#pragma unroll
    for (int q = 0; q < 8; q++) CVT_F16X2(hp[q], val[2 * q], val[2 * q + 1]);
    uint4* pd = (uint4*)(g_WTf16 + (size_t)c * NN + n0);
    pd[0] = make_uint4(hp[0], hp[1], hp[2], hp[3]);
    pd[1] = make_uint4(hp[4], hp[5], hp[6], hp[7]);
}

// ---------------------------------------------------------------------------
// Kernel 1b: scores + exp precompute
// ---------------------------------------------------------------------------
__global__ __launch_bounds__(256) void k_scores(const float* __restrict__ a)
{
    const int gw   = (blockIdx.x * blockDim.x + threadIdx.x) >> 5;
    const int lane = threadIdx.x & 31;
    const int n = gw >> 2, head = gw & 3;

    float2 wv = *(const float2*)(g_Wht + n * COLS + head * HDIM + lane * 2);
    float a1x = a[lane * 2],      a1y = a[lane * 2 + 1];
    float a2x = a[64 + lane * 2], a2y = a[64 + lane * 2 + 1];
    float p1 = wv.x * a1x + wv.y * a1y;
    float p2 = wv.x * a2x + wv.y * a2y;
#pragma unroll
    for (int off = 16; off > 0; off >>= 1) {
        p1 += __shfl_xor_sync(0xFFFFFFFFu, p1, off);
        p2 += __shfl_xor_sync(0xFFFFFFFFu, p2, off);
    }
    if (lane == 0) {
        g_S1 [n * NHEAD + head] = make_float4(p1, expf(p1), expf(0.2f * p1), 0.0f);
        g_EFS[n * NHEAD + head] = make_float4(p2, expf(p2), expf(0.2f * p2), 0.0f);
    }
}

// ---------------------------------------------------------------------------
// Kernel 2: HMMA attention aggregation. grid = (NN/TI)*JS = 1024, 256 thr.
// Warp w owns rows i0 + w*16 .. +15; computes all 4 heads x 64 cols.
// Single-fp16 weight plane (no hi/lo split).
// ---------------------------------------------------------------------------
__global__ __launch_bounds__(256, 1) void k_attn(const int* __restrict__ adj)
{
    extern __shared__ __align__(16) char dsm[];
    const uint32_t sb = smem_u32(dsm);
    const uint32_t ab = (sb + 1023u) & ~1023u;
    char* abp = dsm + (ab - sb);

    const int t    = threadIdx.x;
    const int wid  = t >> 5;
    const int lane = t & 31;
    const int g    = lane >> 2;
    const int tg   = lane & 3;
    const int bx = blockIdx.x;
    const int js    = bx & (JS - 1);
    const int itile = bx >> 4;
    const int i0     = itile * TI;
    const int j0base = js * (NN / JS);

    const int ilA = wid * 16 + g;          // local row A
    const int iA  = i0 + ilA;              // global row A (B = +8)

    // stage S1 once (visible after first barrier)
    for (int idx = t; idx < TI * NHEAD; idx += 256)
        *(float4*)(abp + OFF_S1 + idx * 16) = g_S1[i0 * NHEAD + idx];

    auto stage = [&](int buf, int j0) {
        // B: 256 c-rows x 64 j fp16; 16B granules, swizzled
#pragma unroll
        for (int v = 0; v < 8; v++) {
            int idx = v * 256 + t;
            int row = idx >> 3, u = idx & 7;
            const __half* src = g_WTf16 + (size_t)row * NN + j0 + u * 8;
            uint32_t dst = ab + OFF_B + buf * 32768 + SMEM_SWZ((uint32_t)(row * 128 + u * 16));
            CP_ASYNC16(dst, src);
        }
        // EFS: 64 j x 4 h float4
        {
            const float4* src = g_EFS + j0 * NHEAD + t;
            uint32_t dst = ab + OFF_EFS + buf * 4096 + t * 16;
            CP_ASYNC16(dst, src);
        }
    };

    stage(0, j0base);
    CP_COMMIT();

    float acc[NHEAD][8][4];
#pragma unroll
    for (int h = 0; h < NHEAD; h++)
#pragma unroll
        for (int nt = 0; nt < 8; nt++)
#pragma unroll
            for (int q = 0; q < 4; q++) acc[h][nt][q] = 0.0f;
    float den[2][NHEAD];
#pragma unroll
    for (int r = 0; r < 2; r++)
#pragma unroll
        for (int h = 0; h < NHEAD; h++) den[r][h] = 0.0f;

    for (int ch = 0; ch < JCH; ch++) {
        const int buf = ch & 1;
        const int j0  = j0base + ch * TJ;

        if (ch + 1 < JCH) { stage(buf ^ 1, j0 + TJ); CP_COMMIT(); }

        // adj bitmasks for this chunk (global loads overlap cp.async wait)
        uint32_t mA = 0, mB = 0;
        {
            const int* ap = adj + (size_t)iA * NN + j0 + tg * 2;
#pragma unroll
            for (int s = 0; s < 4; s++) {
                int2 a0 = *(const int2*)(ap + s * 16);
                int2 a1 = *(const int2*)(ap + s * 16 + 8);
                int2 b0 = *(const int2*)(ap + (size_t)8 * NN + s * 16);
                int2 b1 = *(const int2*)(ap + (size_t)8 * NN + s * 16 + 8);
                mA |= (uint32_t)(a0.x & 1) << (s * 4) | (uint32_t)(a0.y & 1) << (s * 4 + 1)
                    | (uint32_t)(a1.x & 1) << (s * 4 + 2) | (uint32_t)(a1.y & 1) << (s * 4 + 3);
                mB |= (uint32_t)(b0.x & 1) << (s * 4) | (uint32_t)(b0.y & 1) << (s * 4 + 1)
                    | (uint32_t)(b1.x & 1) << (s * 4 + 2) | (uint32_t)(b1.y & 1) << (s * 4 + 3);
            }
        }

        if (ch + 1 < JCH) CP_WAIT(1); else CP_WAIT(0);
        __syncthreads();

        const float4* efs = (const float4*)(abp + OFF_EFS + buf * 4096);
        const uint32_t Bb = ab + OFF_B + buf * 32768;

        const int r_c = lane & 7;
        const int jo  = ((lane >> 3) & 3) * 8;   // 0,8,16,24

#pragma unroll
        for (int h = 0; h < NHEAD; h++) {
            float4 sva = *(const float4*)(abp + OFF_S1 + ((ilA) * 4 + h) * 16);
            float4 svb = *(const float4*)(abp + OFF_S1 + ((ilA + 8) * 4 + h) * 16);

#pragma unroll
            for (int sp = 0; sp < 2; sp++) {
                // B fragments: 8 n-tiles x (2 ksteps x 2 regs)
                uint32_t bfr[8][4];
#pragma unroll
                for (int nt = 0; nt < 8; nt++) {
                    uint32_t addr = Bb + (uint32_t)(h * 8192)
                        + SMEM_SWZ((uint32_t)((nt * 8 + r_c) * 128 + (sp * 32 + jo) * 2));
                    LDSM4(bfr[nt], addr);
                }
                // A fragments (single fp16 plane) for 2 ksteps
                uint32_t ahi[2][4];
#pragma unroll
                for (int k2 = 0; k2 < 2; k2++) {
                    const int s  = sp * 2 + k2;
                    const int jj = s * 16 + tg * 2;
                    float4 e0 = efs[(jj)     * 4 + h];
                    float4 e1 = efs[(jj + 1) * 4 + h];
                    float4 e2 = efs[(jj + 8) * 4 + h];
                    float4 e3 = efs[(jj + 9) * 4 + h];

                    float wA0, wA1, wA2, wA3, wB0, wB1, wB2, wB3;
                    {
                        float x;
                        x = sva.x + e0.x; wA0 = ((mA >> (s*4+0)) & 1) ? (x > 0.f ? sva.y*e0.y : sva.z*e0.z) : 0.f;
                        x = sva.x + e1.x; wA1 = ((mA >> (s*4+1)) & 1) ? (x > 0.f ? sva.y*e1.y : sva.z*e1.z) : 0.f;
                        x = sva.x + e2.x; wA2 = ((mA >> (s*4+2)) & 1) ? (x > 0.f ? sva.y*e2.y : sva.z*e2.z) : 0.f;
                        x = sva.x + e3.x; wA3 = ((mA >> (s*4+3)) & 1) ? (x > 0.f ? sva.y*e3.y : sva.z*e3.z) : 0.f;
                        x = svb.x + e0.x; wB0 = ((mB >> (s*4+0)) & 1) ? (x > 0.f ? svb.y*e0.y : svb.z*e0.z) : 0.f;
                        x = svb.x + e1.x; wB1 = ((mB >> (s*4+1)) & 1) ? (x > 0.f ? svb.y*e1.y : svb.z*e1.z) : 0.f;
                        x = svb.x + e2.x; wB2 = ((mB >> (s*4+2)) & 1) ? (x > 0.f ? svb.y*e2.y : svb.z*e2.z) : 0.f;
                        x = svb.x + e3.x; wB3 = ((mB >> (s*4+3)) & 1) ? (x > 0.f ? svb.y*e3.y : svb.z*e3.z) : 0.f;
                    }
                    den[0][h] += (wA0 + wA1) + (wA2 + wA3);
                    den[1][h] += (wB0 + wB1) + (wB2 + wB3);

                    CVT_F16X2(ahi[k2][0], wA0, wA1);
                    CVT_F16X2(ahi[k2][1], wB0, wB1);
                    CVT_F16X2(ahi[k2][2], wA2, wA3);
                    CVT_F16X2(ahi[k2][3], wB2, wB3);
                }
                // MMAs (single plane)
#pragma unroll
                for (int nt = 0; nt < 8; nt++) {
#pragma unroll
                    for (int k2 = 0; k2 < 2; k2++) {
                        MMA16816(acc[h][nt], ahi[k2][0], ahi[k2][1], ahi[k2][2], ahi[k2][3],
                                 bfr[nt][k2 * 2], bfr[nt][k2 * 2 + 1]);
                    }
                }
            }
        }
        __syncthreads();
    }

    // ---- epilogue ----
#pragma unroll
    for (int r = 0; r < 2; r++)
#pragma unroll
        for (int h = 0; h < NHEAD; h++) {
            den[r][h] += __shfl_xor_sync(0xFFFFFFFFu, den[r][h], 1);
            den[r][h] += __shfl_xor_sync(0xFFFFFFFFu, den[r][h], 2);
        }
    if (tg == 0) {
        *(float4*)(g_denP + ((size_t)js * NN + iA)     * NHEAD) =
            make_float4(den[0][0], den[0][1], den[0][2], den[0][3]);
        *(float4*)(g_denP + ((size_t)js * NN + iA + 8) * NHEAD) =
            make_float4(den[1][0], den[1][1], den[1][2], den[1][3]);
    }
#pragma unroll
    for (int h = 0; h < NHEAD; h++)
#pragma unroll
        for (int nt = 0; nt < 8; nt++) {
            const int c0 = h * 64 + nt * 8 + tg * 2;
            *(float2*)(g_outP + ((size_t)js * NN + iA)     * COLS + c0) =
                make_float2(acc[h][nt][0], acc[h][nt][1]);
            *(float2*)(g_outP + ((size_t)js * NN + iA + 8) * COLS + c0) =
                make_float2(acc[h][nt][2], acc[h][nt][3]);
        }
}

// ---------------------------------------------------------------------------
// Kernel 3: combine j-split partials
// ---------------------------------------------------------------------------
__global__ __launch_bounds__(256) void k_comb(float* __restrict__ out)
{
    const int idx = blockIdx.x * 256 + threadIdx.x;   // float4 index over NN*64
    const int i  = idx >> 6;
    const int c4 = idx & 63;
    const int h  = c4 >> 4;

    float4 s = make_float4(0.f, 0.f, 0.f, 0.f);
    float d = 0.f;
#pragma unroll
    for (int js = 0; js < JS; js++) {
        float4 p = ((const float4*)g_outP)[((size_t)js * NN + i) * 64 + c4];
        s.x += p.x; s.y += p.y; s.z += p.z; s.w += p.w;
        d += g_denP[((size_t)js * NN + i) * NHEAD + h];
    }
    float inv = 1.0f / d;
    ((float4*)out)[idx] = make_float4(s.x * inv, s.y * inv, s.z * inv, s.w * inv);
}

// ---------------------------------------------------------------------------
extern "C" void kernel_launch(void* const* d_in, const int* in_sizes, int n_in,
                              void* d_out, int out_size)
{
    const float* hmat = (const float*)d_in[0];   // [8192, 256] f32
    const int*   adj  = (const int*)  d_in[1];   // [8192, 8192] i32
    const float* W    = (const float*)d_in[2];   // [4, 256, 64] f32
    const float* a    = (const float*)d_in[3];   // [128, 1] f32
    float* out = (float*)d_out;                  // [8192, 256] f32

    cudaFuncSetAttribute(k_attn, cudaFuncAttributeMaxDynamicSharedMemorySize, SMEM_REQ);

    k_gemm  <<<NN / 16, 256>>>(hmat, W);
    k_scores<<<(NN * NHEAD) / 8, 256>>>(a);
    k_attn  <<<(NN / TI) * JS, 256, SMEM_REQ>>>(adj);
    k_comb  <<<(NN * 64) / 256, 256>>>(out);
}

// round 6
// speedup vs baseline: 4.4462x; 1.0701x over previous
#include <cuda_runtime.h>
#include <cuda_fp16.h>
#include <cstdint>

// Problem constants
#define NN       8192
#define IN_DIM   256
#define NHEAD    4
#define HDIM     64
#define COLS     256   // NHEAD*HDIM

// attention tiling
#define TI   64                    // rows per block
#define TJ   64                    // j per chunk (K)
#define JS   16                    // j-splits
#define JCH  ((NN / JS) / TJ)      // 8 chunks per block

// smem byte offsets (from 1024-aligned base)
#define OFF_B     0u               // 2 bufs x 32768 (4 heads x 64 c-rows x 128B fp16)
#define OFF_EFS   65536u           // 2 bufs x 4096  (64 j x 4 h x float4)
#define OFF_S1    73728u           // 4096 (64 i x 4 h x float4)
#define SMEM_REQ  (77824u + 1024u)

#define SMEM_SWZ(off) ((off) ^ (((off) >> 3) & 0x70u))

// ---------------- PTX helpers ----------------
__device__ __forceinline__ uint32_t smem_u32(const void* p) {
    uint32_t a;
    asm("{ .reg .u64 t; cvta.to.shared.u64 t, %1; cvt.u32.u64 %0, t; }" : "=r"(a) : "l"(p));
    return a;
}
#define PACK2(out, lo, hi) \
    asm("mov.b64 %0, {%1, %2};" : "=l"(out) : "f"(lo), "f"(hi))
#define UNPACK2(lo, hi, in) \
    asm("mov.b64 {%0, %1}, %2;" : "=f"(lo), "=f"(hi) : "l"(in))
#define FMA2(d, a, b, c) \
    asm("fma.rn.f32x2 %0, %1, %2, %3;" : "=l"(d) : "l"(a), "l"(b), "l"(c))
// pack two f32 -> f16x2 (lo in low half)
#define CVT_F16X2(r, lo, hi) \
    asm("cvt.rn.f16x2.f32 %0, %1, %2;" : "=r"(r) : "f"(hi), "f"(lo))

#define CP_ASYNC16(dst, src) \
    asm volatile("cp.async.cg.shared.global [%0], [%1], 16;" :: "r"(dst), "l"(src))
#define CP_COMMIT() asm volatile("cp.async.commit_group;" ::: "memory")
#define CP_WAIT(n)  asm volatile("cp.async.wait_group %0;" :: "n"(n) : "memory")

#define LDSM4(r, addr) \
    asm volatile("ldmatrix.sync.aligned.m8n8.x4.shared.b16 {%0,%1,%2,%3}, [%4];" \
        : "=r"((r)[0]), "=r"((r)[1]), "=r"((r)[2]), "=r"((r)[3]) : "r"(addr))

#define MMA16816(d, a0, a1, a2, a3, b0, b1) \
    asm volatile("mma.sync.aligned.m16n8k16.row.col.f32.f16.f16.f32 " \
        "{%0,%1,%2,%3}, {%4,%5,%6,%7}, {%8,%9}, {%0,%1,%2,%3};" \
        : "+f"((d)[0]), "+f"((d)[1]), "+f"((d)[2]), "+f"((d)[3]) \
        : "r"(a0), "r"(a1), "r"(a2), "r"(a3), "r"(b0), "r"(b1))

// ---------------- scratch globals ----------------
__device__ float   g_Wht[NN * COLS];            // Wh fp32 [n][c] (for scores)
__device__ __half  g_WTf16[COLS * NN];          // Wh^T fp16 [c][j]  (4 MB)
__device__ float4  g_S1[NN * NHEAD];            // {s1, e^s1, e^{.2 s1}, 0}
__device__ float4  g_EFS[NN * NHEAD];           // {s2, e^s2, e^{.2 s2}, 0}
__device__ float   g_outP[(size_t)JS * NN * COLS];
__device__ float   g_denP[(size_t)JS * NN * NHEAD];

// ---------------------------------------------------------------------------
// Kernel 1: Wh = h @ W ; also emit fp16 Wh^T plane.
// ---------------------------------------------------------------------------
__global__ __launch_bounds__(256) void k_gemm(const float* __restrict__ hmat,
                                              const float* __restrict__ W)
{
    __shared__ __align__(16) float hsT[IN_DIM][18];
    const int n0 = blockIdx.x * 16;
    const int t  = threadIdx.x;

    for (int q = t; q < 1024; q += 256) {
        int row = q >> 6, kq = q & 63;
        float4 v = *(const float4*)(hmat + (n0 + row) * IN_DIM + kq * 4);
        hsT[kq * 4 + 0][row] = v.x;
        hsT[kq * 4 + 1][row] = v.y;
        hsT[kq * 4 + 2][row] = v.z;
        hsT[kq * 4 + 3][row] = v.w;
    }
    __syncthreads();

    const int c = t;
    const int head = c >> 6, d = c & 63;
    const float* Wp = W + head * (IN_DIM * HDIM) + d;

    unsigned long long acc[8];
#pragma unroll
    for (int rp = 0; rp < 8; rp++) acc[rp] = 0ull;

#pragma unroll 4
    for (int k = 0; k < IN_DIM; k++) {
        float wv = Wp[k * HDIM];
        unsigned long long ws;
        PACK2(ws, wv, wv);
#pragma unroll
        for (int rp = 0; rp < 8; rp++) {
            unsigned long long hv = *(const unsigned long long*)&hsT[k][rp * 2];
            FMA2(acc[rp], hv, ws, acc[rp]);
        }
    }

    float val[16];
#pragma unroll
    for (int rp = 0; rp < 8; rp++) {
        UNPACK2(val[2 * rp], val[2 * rp + 1], acc[rp]);
        g_Wht[(n0 + 2 * rp + 0) * COLS + c] = val[2 * rp];
        g_Wht[(n0 + 2 * rp + 1) * COLS + c] = val[2 * rp + 1];
    }
    uint32_t hp[8];
#pragma unroll
    for (int q = 0; q < 8; q++) CVT_F16X2(hp[q], val[2 * q], val[2 * q + 1]);
    uint4* pd = (uint4*)(g_WTf16 + (size_t)c * NN + n0);
    pd[0] = make_uint4(hp[0], hp[1], hp[2], hp[3]);
    pd[1] = make_uint4(hp[4], hp[5], hp[6], hp[7]);
}

// ---------------------------------------------------------------------------
// Kernel 1b: scores + exp precompute
// ---------------------------------------------------------------------------
__global__ __launch_bounds__(256) void k_scores(const float* __restrict__ a)
{
    const int gw   = (blockIdx.x * blockDim.x + threadIdx.x) >> 5;
    const int lane = threadIdx.x & 31;
    const int n = gw >> 2, head = gw & 3;

    float2 wv = *(const float2*)(g_Wht + n * COLS + head * HDIM + lane * 2);
    float a1x = a[lane * 2],      a1y = a[lane * 2 + 1];
    float a2x = a[64 + lane * 2], a2y = a[64 + lane * 2 + 1];
    float p1 = wv.x * a1x + wv.y * a1y;
    float p2 = wv.x * a2x + wv.y * a2y;
#pragma unroll
    for (int off = 16; off > 0; off >>= 1) {
        p1 += __shfl_xor_sync(0xFFFFFFFFu, p1, off);
        p2 += __shfl_xor_sync(0xFFFFFFFFu, p2, off);
    }
    if (lane == 0) {
        g_S1 [n * NHEAD + head] = make_float4(p1, expf(p1), expf(0.2f * p1), 0.0f);
        g_EFS[n * NHEAD + head] = make_float4(p2, expf(p2), expf(0.2f * p2), 0.0f);
    }
}

// ---------------------------------------------------------------------------
// Kernel 2: HMMA attention aggregation. grid = (NN/TI)*JS = 2048, 256 thr,
// 2 blocks/SM. Warp = 16 rows x 2 heads: rg = wid>>1, headpair = wid&1.
// ---------------------------------------------------------------------------
__global__ __launch_bounds__(256, 2) void k_attn(const int* __restrict__ adj)
{
    extern __shared__ __align__(16) char dsm[];
    const uint32_t sb = smem_u32(dsm);
    const uint32_t ab = (sb + 1023u) & ~1023u;
    char* abp = dsm + (ab - sb);

    const int t    = threadIdx.x;
    const int wid  = t >> 5;
    const int lane = t & 31;
    const int g    = lane >> 2;
    const int tg   = lane & 3;
    const int rg    = wid >> 1;        // rowgroup 0..3
    const int hpair = wid & 1;         // heads hpair*2, hpair*2+1
    const int bx = blockIdx.x;
    const int js    = bx & (JS - 1);
    const int itile = bx >> 4;
    const int i0     = itile * TI;
    const int j0base = js * (NN / JS);

    const int ilA = rg * 16 + g;           // local row A
    const int iA  = i0 + ilA;              // global row A (B = +8)

    // stage S1 once (visible after first barrier): 64 i x 4 h float4
    *(float4*)(abp + OFF_S1 + t * 16) = g_S1[i0 * NHEAD + t];

    auto stage = [&](int buf, int j0) {
        // B: 256 c-rows x 64 j fp16; 16B granules, swizzled
#pragma unroll
        for (int v = 0; v < 8; v++) {
            int idx = v * 256 + t;
            int row = idx >> 3, u = idx & 7;
            const __half* src = g_WTf16 + (size_t)row * NN + j0 + u * 8;
            uint32_t dst = ab + OFF_B + buf * 32768 + SMEM_SWZ((uint32_t)(row * 128 + u * 16));
            CP_ASYNC16(dst, src);
        }
        // EFS: 64 j x 4 h float4
        {
            const float4* src = g_EFS + j0 * NHEAD + t;
            uint32_t dst = ab + OFF_EFS + buf * 4096 + t * 16;
            CP_ASYNC16(dst, src);
        }
    };

    stage(0, j0base);
    CP_COMMIT();

    float acc[2][8][4];
#pragma unroll
    for (int hh = 0; hh < 2; hh++)
#pragma unroll
        for (int nt = 0; nt < 8; nt++)
#pragma unroll
            for (int q = 0; q < 4; q++) acc[hh][nt][q] = 0.0f;
    float den[2][2];
    den[0][0] = den[0][1] = den[1][0] = den[1][1] = 0.0f;

    for (int ch = 0; ch < JCH; ch++) {
        const int buf = ch & 1;
        const int j0  = j0base + ch * TJ;

        if (ch + 1 < JCH) { stage(buf ^ 1, j0 + TJ); CP_COMMIT(); }

        // adj bitmasks for this chunk (both head-warps of a rowgroup load the
        // same lines; second one hits L1)
        uint32_t mA = 0, mB = 0;
        {
            const int* ap = adj + (size_t)iA * NN + j0 + tg * 2;
#pragma unroll
            for (int s = 0; s < 4; s++) {
                int2 a0 = *(const int2*)(ap + s * 16);
                int2 a1 = *(const int2*)(ap + s * 16 + 8);
                int2 b0 = *(const int2*)(ap + (size_t)8 * NN + s * 16);
                int2 b1 = *(const int2*)(ap + (size_t)8 * NN + s * 16 + 8);
                mA |= (uint32_t)(a0.x & 1) << (s * 4) | (uint32_t)(a0.y & 1) << (s * 4 + 1)
                    | (uint32_t)(a1.x & 1) << (s * 4 + 2) | (uint32_t)(a1.y & 1) << (s * 4 + 3);
                mB |= (uint32_t)(b0.x & 1) << (s * 4) | (uint32_t)(b0.y & 1) << (s * 4 + 1)
                    | (uint32_t)(b1.x & 1) << (s * 4 + 2) | (uint32_t)(b1.y & 1) << (s * 4 + 3);
            }
        }

        if (ch + 1 < JCH) CP_WAIT(1); else CP_WAIT(0);
        __syncthreads();

        const float4* efs = (const float4*)(abp + OFF_EFS + buf * 4096);
        const uint32_t Bb = ab + OFF_B + buf * 32768;

        const int r_c = lane & 7;
        const int jo  = ((lane >> 3) & 3) * 8;   // 0,8,16,24

#pragma unroll
        for (int hh = 0; hh < 2; hh++) {
            const int h = hpair * 2 + hh;
            float4 sva = *(const float4*)(abp + OFF_S1 + ((ilA) * 4 + h) * 16);
            float4 svb = *(const float4*)(abp + OFF_S1 + ((ilA + 8) * 4 + h) * 16);

#pragma unroll
            for (int sp = 0; sp < 2; sp++) {
                // A fragments (single fp16 plane) for 2 ksteps
                uint32_t ahi[2][4];
#pragma unroll
                for (int k2 = 0; k2 < 2; k2++) {
                    const int s  = sp * 2 + k2;
                    const int jj = s * 16 + tg * 2;
                    float4 e0 = efs[(jj)     * 4 + h];
                    float4 e1 = efs[(jj + 1) * 4 + h];
                    float4 e2 = efs[(jj + 8) * 4 + h];
                    float4 e3 = efs[(jj + 9) * 4 + h];

                    float wA0, wA1, wA2, wA3, wB0, wB1, wB2, wB3;
                    {
                        float x;
                        x = sva.x + e0.x; wA0 = ((mA >> (s*4+0)) & 1) ? (x > 0.f ? sva.y*e0.y : sva.z*e0.z) : 0.f;
                        x = sva.x + e1.x; wA1 = ((mA >> (s*4+1)) & 1) ? (x > 0.f ? sva.y*e1.y : sva.z*e1.z) : 0.f;
                        x = sva.x + e2.x; wA2 = ((mA >> (s*4+2)) & 1) ? (x > 0.f ? sva.y*e2.y : sva.z*e2.z) : 0.f;
                        x = sva.x + e3.x; wA3 = ((mA >> (s*4+3)) & 1) ? (x > 0.f ? sva.y*e3.y : sva.z*e3.z) : 0.f;
                        x = svb.x + e0.x; wB0 = ((mB >> (s*4+0)) & 1) ? (x > 0.f ? svb.y*e0.y : svb.z*e0.z) : 0.f;
                        x = svb.x + e1.x; wB1 = ((mB >> (s*4+1)) & 1) ? (x > 0.f ? svb.y*e1.y : svb.z*e1.z) : 0.f;
                        x = svb.x + e2.x; wB2 = ((mB >> (s*4+2)) & 1) ? (x > 0.f ? svb.y*e2.y : svb.z*e2.z) : 0.f;
                        x = svb.x + e3.x; wB3 = ((mB >> (s*4+3)) & 1) ? (x > 0.f ? svb.y*e3.y : svb.z*e3.z) : 0.f;
                    }
                    den[0][hh] += (wA0 + wA1) + (wA2 + wA3);
                    den[1][hh] += (wB0 + wB1) + (wB2 + wB3);

                    CVT_F16X2(ahi[k2][0], wA0, wA1);
                    CVT_F16X2(ahi[k2][1], wB0, wB1);
                    CVT_F16X2(ahi[k2][2], wA2, wA3);
                    CVT_F16X2(ahi[k2][3], wB2, wB3);
                }
                // B fragments + MMAs in quads (bfr footprint 16 regs)
#pragma unroll
                for (int ntq = 0; ntq < 2; ntq++) {
                    uint32_t bfr[4][4];
#pragma unroll
                    for (int q = 0; q < 4; q++) {
                        int nt = ntq * 4 + q;
                        uint32_t addr = Bb + (uint32_t)(h * 8192)
                            + SMEM_SWZ((uint32_t)((nt * 8 + r_c) * 128 + (sp * 32 + jo) * 2));
                        LDSM4(bfr[q], addr);
                    }
#pragma unroll
                    for (int q = 0; q < 4; q++) {
#pragma unroll
                        for (int k2 = 0; k2 < 2; k2++) {
                            MMA16816(acc[hh][ntq * 4 + q],
                                     ahi[k2][0], ahi[k2][1], ahi[k2][2], ahi[k2][3],
                                     bfr[q][k2 * 2], bfr[q][k2 * 2 + 1]);
                        }
                    }
                }
            }
        }
        __syncthreads();
    }

    // ---- epilogue ----
#pragma unroll
    for (int r = 0; r < 2; r++)
#pragma unroll
        for (int hh = 0; hh < 2; hh++) {
            den[r][hh] += __shfl_xor_sync(0xFFFFFFFFu, den[r][hh], 1);
            den[r][hh] += __shfl_xor_sync(0xFFFFFFFFu, den[r][hh], 2);
        }
    if (tg == 0) {
        *(float2*)(g_denP + ((size_t)js * NN + iA)     * NHEAD + hpair * 2) =
            make_float2(den[0][0], den[0][1]);
        *(float2*)(g_denP + ((size_t)js * NN + iA + 8) * NHEAD + hpair * 2) =
            make_float2(den[1][0], den[1][1]);
    }
#pragma unroll
    for (int hh = 0; hh < 2; hh++) {
        const int h = hpair * 2 + hh;
#pragma unroll
        for (int nt = 0; nt < 8; nt++) {
            const int c0 = h * 64 + nt * 8 + tg * 2;
            *(float2*)(g_outP + ((size_t)js * NN + iA)     * COLS + c0) =
                make_float2(acc[hh][nt][0], acc[hh][nt][1]);
            *(float2*)(g_outP + ((size_t)js * NN + iA + 8) * COLS + c0) =
                make_float2(acc[hh][nt][2], acc[hh][nt][3]);
        }
    }
}

// ---------------------------------------------------------------------------
// Kernel 3: combine j-split partials
// ---------------------------------------------------------------------------
__global__ __launch_bounds__(256) void k_comb(float* __restrict__ out)
{
    const int idx = blockIdx.x * 256 + threadIdx.x;   // float4 index over NN*64
    const int i  = idx >> 6;
    const int c4 = idx & 63;
    const int h  = c4 >> 4;

    float4 s = make_float4(0.f, 0.f, 0.f, 0.f);
    float d = 0.f;
#pragma unroll
    for (int js = 0; js < JS; js++) {
        float4 p = ((const float4*)g_outP)[((size_t)js * NN + i) * 64 + c4];
        s.x += p.x; s.y += p.y; s.z += p.z; s.w += p.w;
        d += g_denP[((size_t)js * NN + i) * NHEAD + h];
    }
    float inv = 1.0f / d;
    ((float4*)out)[idx] = make_float4(s.x * inv, s.y * inv, s.z * inv, s.w * inv);
}

// ---------------------------------------------------------------------------
extern "C" void kernel_launch(void* const* d_in, const int* in_sizes, int n_in,
                              void* d_out, int out_size)
{
    const float* hmat = (const float*)d_in[0];   // [8192, 256] f32
    const int*   adj  = (const int*)  d_in[1];   // [8192, 8192] i32
    const float* W    = (const float*)d_in[2];   // [4, 256, 64] f32
    const float* a    = (const float*)d_in[3];   // [128, 1] f32
    float* out = (float*)d_out;                  // [8192, 256] f32

    cudaFuncSetAttribute(k_attn, cudaFuncAttributeMaxDynamicSharedMemorySize, SMEM_REQ);

    k_gemm  <<<NN / 16, 256>>>(hmat, W);
    k_scores<<<(NN * NHEAD) / 8, 256>>>(a);
    k_attn  <<<(NN / TI) * JS, 256, SMEM_REQ>>>(adj);
    k_comb  <<<(NN * 64) / 256, 256>>>(out);
}

// round 7
// speedup vs baseline: 8.0914x; 1.8198x over previous
#include <cuda_runtime.h>
#include <cuda_fp16.h>
#include <cstdint>

// Problem constants
#define NN       8192
#define IN_DIM   256
#define NHEAD    4
#define HDIM     64
#define COLS     256   // NHEAD*HDIM

// attention tiling
#define TI   64                    // rows per block
#define TJ   64                    // j per chunk (K)
#define JS   16                    // j-splits
#define JCH  ((NN / JS) / TJ)      // 8 chunks per block

// smem byte offsets (from 1024-aligned base)
#define OFF_B     0u               // 2 bufs x 32768 (256 c-rows x 64 j fp16, SW128)
#define OFF_EFS   65536u           // 2 bufs x 2048  ([h][64 j] float2 {E2,F2})
#define OFF_S1    69632u           // 2048 (64 i x 4 h float2 {E1,F1})
#define SMEM_REQ  (71680u + 1024u)

#define SMEM_SWZ(off) ((off) ^ (((off) >> 3) & 0x70u))

// ---------------- PTX helpers ----------------
__device__ __forceinline__ uint32_t smem_u32(const void* p) {
    uint32_t a;
    asm("{ .reg .u64 t; cvta.to.shared.u64 t, %1; cvt.u32.u64 %0, t; }" : "=r"(a) : "l"(p));
    return a;
}
#define PACK2(out, lo, hi) \
    asm("mov.b64 %0, {%1, %2};" : "=l"(out) : "f"(lo), "f"(hi))
#define UNPACK2(lo, hi, in) \
    asm("mov.b64 {%0, %1}, %2;" : "=f"(lo), "=f"(hi) : "l"(in))
#define FMA2(d, a, b, c) \
    asm("fma.rn.f32x2 %0, %1, %2, %3;" : "=l"(d) : "l"(a), "l"(b), "l"(c))
// pack two f32 -> f16x2 (lo in low half)
#define CVT_F16X2(r, lo, hi) \
    asm("cvt.rn.f16x2.f32 %0, %1, %2;" : "=r"(r) : "f"(hi), "f"(lo))

#define CP_ASYNC16(dst, src) \
    asm volatile("cp.async.cg.shared.global [%0], [%1], 16;" :: "r"(dst), "l"(src))
#define CP_ASYNC8(dst, src) \
    asm volatile("cp.async.ca.shared.global [%0], [%1], 8;" :: "r"(dst), "l"(src))
#define CP_COMMIT() asm volatile("cp.async.commit_group;" ::: "memory")
#define CP_WAIT(n)  asm volatile("cp.async.wait_group %0;" :: "n"(n) : "memory")

#define LDSM4(r, addr) \
    asm volatile("ldmatrix.sync.aligned.m8n8.x4.shared.b16 {%0,%1,%2,%3}, [%4];" \
        : "=r"((r)[0]), "=r"((r)[1]), "=r"((r)[2]), "=r"((r)[3]) : "r"(addr))

#define MMA16816(d, a0, a1, a2, a3, b0, b1) \
    asm volatile("mma.sync.aligned.m16n8k16.row.col.f32.f16.f16.f32 " \
        "{%0,%1,%2,%3}, {%4,%5,%6,%7}, {%8,%9}, {%0,%1,%2,%3};" \
        : "+f"((d)[0]), "+f"((d)[1]), "+f"((d)[2]), "+f"((d)[3]) \
        : "r"(a0), "r"(a1), "r"(a2), "r"(a3), "r"(b0), "r"(b1))

// masked-max weight: max(E1*E2, F1*F2) & sext(bit)
__device__ __forceinline__ float wmax_masked(float E1, float F1, float E2, float F2,
                                             uint32_t m, int k) {
    float v = fmaxf(E1 * E2, F1 * F2);
    return __int_as_float(__float_as_int(v) & (-(int)((m >> k) & 1u)));
}

// ---------------- scratch globals ----------------
__device__ float   g_Wht[NN * COLS];            // Wh fp32 [n][c] (for scores)
__device__ __half  g_WTf16[COLS * NN];          // Wh^T fp16 [c][j]  (4 MB)
__device__ float2  g_S12[NN * NHEAD];           // {e^s1, e^{.2 s1}}
__device__ float2  g_EFS2[NN * NHEAD];          // {e^s2, e^{.2 s2}}
__device__ float   g_outP[(size_t)JS * NN * COLS];
__device__ float   g_denP[(size_t)JS * NN * NHEAD];

// ---------------------------------------------------------------------------
// Kernel 1: Wh = h @ W ; also emit fp16 Wh^T plane.
// ---------------------------------------------------------------------------
__global__ __launch_bounds__(256) void k_gemm(const float* __restrict__ hmat,
                                              const float* __restrict__ W)
{
    __shared__ __align__(16) float hsT[IN_DIM][18];
    const int n0 = blockIdx.x * 16;
    const int t  = threadIdx.x;

    for (int q = t; q < 1024; q += 256) {
        int row = q >> 6, kq = q & 63;
        float4 v = *(const float4*)(hmat + (n0 + row) * IN_DIM + kq * 4);
        hsT[kq * 4 + 0][row] = v.x;
        hsT[kq * 4 + 1][row] = v.y;
        hsT[kq * 4 + 2][row] = v.z;
        hsT[kq * 4 + 3][row] = v.w;
    }
    __syncthreads();

    const int c = t;
    const int head = c >> 6, d = c & 63;
    const float* Wp = W + head * (IN_DIM * HDIM) + d;

    unsigned long long acc[8];
#pragma unroll
    for (int rp = 0; rp < 8; rp++) acc[rp] = 0ull;

#pragma unroll 4
    for (int k = 0; k < IN_DIM; k++) {
        float wv = Wp[k * HDIM];
        unsigned long long ws;
        PACK2(ws, wv, wv);
#pragma unroll
        for (int rp = 0; rp < 8; rp++) {
            unsigned long long hv = *(const unsigned long long*)&hsT[k][rp * 2];
            FMA2(acc[rp], hv, ws, acc[rp]);
        }
    }

    float val[16];
#pragma unroll
    for (int rp = 0; rp < 8; rp++) {
        UNPACK2(val[2 * rp], val[2 * rp + 1], acc[rp]);
        g_Wht[(n0 + 2 * rp + 0) * COLS + c] = val[2 * rp];
        g_Wht[(n0 + 2 * rp + 1) * COLS + c] = val[2 * rp + 1];
    }
    uint32_t hp[8];
#pragma unroll
    for (int q = 0; q < 8; q++) CVT_F16X2(hp[q], val[2 * q], val[2 * q + 1]);
    uint4* pd = (uint4*)(g_WTf16 + (size_t)c * NN + n0);
    pd[0] = make_uint4(hp[0], hp[1], hp[2], hp[3]);
    pd[1] = make_uint4(hp[4], hp[5], hp[6], hp[7]);
}

// ---------------------------------------------------------------------------
// Kernel 1b: scores + exp precompute ({E, F} pairs only)
// ---------------------------------------------------------------------------
__global__ __launch_bounds__(256) void k_scores(const float* __restrict__ a)
{
    const int gw   = (blockIdx.x * blockDim.x + threadIdx.x) >> 5;
    const int lane = threadIdx.x & 31;
    const int n = gw >> 2, head = gw & 3;

    float2 wv = *(const float2*)(g_Wht + n * COLS + head * HDIM + lane * 2);
    float a1x = a[lane * 2],      a1y = a[lane * 2 + 1];
    float a2x = a[64 + lane * 2], a2y = a[64 + lane * 2 + 1];
    float p1 = wv.x * a1x + wv.y * a1y;
    float p2 = wv.x * a2x + wv.y * a2y;
#pragma unroll
    for (int off = 16; off > 0; off >>= 1) {
        p1 += __shfl_xor_sync(0xFFFFFFFFu, p1, off);
        p2 += __shfl_xor_sync(0xFFFFFFFFu, p2, off);
    }
    if (lane == 0) {
        g_S12 [n * NHEAD + head] = make_float2(expf(p1), expf(0.2f * p1));
        g_EFS2[n * NHEAD + head] = make_float2(expf(p2), expf(0.2f * p2));
    }
}

// ---------------------------------------------------------------------------
// Kernel 2: HMMA attention aggregation. grid = (NN/TI)*JS = 2048, 256 thr,
// 2 blocks/SM. Warp = 16 rows x 2 heads. Flat-ILP weight phase via
// exp(lrelu(x)) == max(E1*E2, F1*F2).
// ---------------------------------------------------------------------------
__global__ __launch_bounds__(256, 2) void k_attn(const int* __restrict__ adj)
{
    extern __shared__ __align__(16) char dsm[];
    const uint32_t sb = smem_u32(dsm);
    const uint32_t ab = (sb + 1023u) & ~1023u;
    char* abp = dsm + (ab - sb);

    const int t    = threadIdx.x;
    const int wid  = t >> 5;
    const int lane = t & 31;
    const int g    = lane >> 2;
    const int tg   = lane & 3;
    const int rg    = wid >> 1;        // rowgroup 0..3
    const int hpair = wid & 1;         // heads hpair*2, hpair*2+1
    const int bx = blockIdx.x;
    const int js    = bx & (JS - 1);
    const int itile = bx >> 4;
    const int i0     = itile * TI;
    const int j0base = js * (NN / JS);

    const int ilA = rg * 16 + g;           // local row A
    const int iA  = i0 + ilA;              // global row A (B = +8)

    // stage S1 {E1,F1} once: 64 i x 4 h float2
    *(float2*)(abp + OFF_S1 + t * 8) = g_S12[i0 * NHEAD + t];

    auto stage = [&](int buf, int j0) {
        // B: 256 c-rows x 64 j fp16; 16B granules, swizzled
#pragma unroll
        for (int v = 0; v < 8; v++) {
            int idx = v * 256 + t;
            int row = idx >> 3, u = idx & 7;
            const __half* src = g_WTf16 + (size_t)row * NN + j0 + u * 8;
            uint32_t dst = ab + OFF_B + buf * 32768 + SMEM_SWZ((uint32_t)(row * 128 + u * 16));
            CP_ASYNC16(dst, src);
        }
        // EFS: transpose to [h][64 j] float2
        {
            int h = t & 3, jl = t >> 2;
            const float2* src = g_EFS2 + (j0 + jl) * NHEAD + h;
            uint32_t dst = ab + OFF_EFS + buf * 2048 + (uint32_t)(h * 64 + jl) * 8;
            CP_ASYNC8(dst, src);
        }
    };

    stage(0, j0base);
    CP_COMMIT();

    float acc[2][8][4];
#pragma unroll
    for (int hh = 0; hh < 2; hh++)
#pragma unroll
        for (int nt = 0; nt < 8; nt++)
#pragma unroll
            for (int q = 0; q < 4; q++) acc[hh][nt][q] = 0.0f;
    float den[2][2];
    den[0][0] = den[0][1] = den[1][0] = den[1][1] = 0.0f;

    for (int ch = 0; ch < JCH; ch++) {
        const int buf = ch & 1;
        const int j0  = j0base + ch * TJ;

        if (ch + 1 < JCH) { stage(buf ^ 1, j0 + TJ); CP_COMMIT(); }

        // adj bitmasks for this chunk
        uint32_t mA = 0, mB = 0;
        {
            const int* ap = adj + (size_t)iA * NN + j0 + tg * 2;
#pragma unroll
            for (int s = 0; s < 4; s++) {
                int2 a0 = *(const int2*)(ap + s * 16);
                int2 a1 = *(const int2*)(ap + s * 16 + 8);
                int2 b0 = *(const int2*)(ap + (size_t)8 * NN + s * 16);
                int2 b1 = *(const int2*)(ap + (size_t)8 * NN + s * 16 + 8);
                mA |= (uint32_t)(a0.x & 1) << (s * 4) | (uint32_t)(a0.y & 1) << (s * 4 + 1)
                    | (uint32_t)(a1.x & 1) << (s * 4 + 2) | (uint32_t)(a1.y & 1) << (s * 4 + 3);
                mB |= (uint32_t)(b0.x & 1) << (s * 4) | (uint32_t)(b0.y & 1) << (s * 4 + 1)
                    | (uint32_t)(b1.x & 1) << (s * 4 + 2) | (uint32_t)(b1.y & 1) << (s * 4 + 3);
            }
        }

        if (ch + 1 < JCH) CP_WAIT(1); else CP_WAIT(0);
        __syncthreads();

        const uint32_t Eb = ab + OFF_EFS + buf * 2048;
        const uint32_t Bb = ab + OFF_B + buf * 32768;

        const int r_c = lane & 7;
        const int jo  = ((lane >> 3) & 3) * 8;   // 0,8,16,24

#pragma unroll
        for (int hh = 0; hh < 2; hh++) {
            const int h = hpair * 2 + hh;
            float2 efA = *(const float2*)(abp + OFF_S1 + ((ilA) * 4 + h) * 8);
            float2 efB = *(const float2*)(abp + OFF_S1 + ((ilA + 8) * 4 + h) * 8);

#pragma unroll
            for (int sp = 0; sp < 2; sp++) {
                // A fragments for 2 ksteps — flat ILP, no branches/selects
                uint32_t ahi[2][4];
#pragma unroll
                for (int k2 = 0; k2 < 2; k2++) {
                    const int s  = sp * 2 + k2;
                    const int jj = s * 16 + tg * 2;
                    // {E2,F2} pairs: (jj, jj+1) and (jj+8, jj+9), conflict-free
                    float4 p01 = *(const float4*)(abp + (Eb - ab) + (uint32_t)(h * 64 + jj) * 8);
                    float4 p89 = *(const float4*)(abp + (Eb - ab) + (uint32_t)(h * 64 + jj + 8) * 8);

                    float wA0 = wmax_masked(efA.x, efA.y, p01.x, p01.y, mA, s * 4 + 0);
                    float wA1 = wmax_masked(efA.x, efA.y, p01.z, p01.w, mA, s * 4 + 1);
                    float wA2 = wmax_masked(efA.x, efA.y, p89.x, p89.y, mA, s * 4 + 2);
                    float wA3 = wmax_masked(efA.x, efA.y, p89.z, p89.w, mA, s * 4 + 3);
                    float wB0 = wmax_masked(efB.x, efB.y, p01.x, p01.y, mB, s * 4 + 0);
                    float wB1 = wmax_masked(efB.x, efB.y, p01.z, p01.w, mB, s * 4 + 1);
                    float wB2 = wmax_masked(efB.x, efB.y, p89.x, p89.y, mB, s * 4 + 2);
                    float wB3 = wmax_masked(efB.x, efB.y, p89.z, p89.w, mB, s * 4 + 3);

                    den[0][hh] += (wA0 + wA1) + (wA2 + wA3);
                    den[1][hh] += (wB0 + wB1) + (wB2 + wB3);

                    CVT_F16X2(ahi[k2][0], wA0, wA1);
                    CVT_F16X2(ahi[k2][1], wB0, wB1);
                    CVT_F16X2(ahi[k2][2], wA2, wA3);
                    CVT_F16X2(ahi[k2][3], wB2, wB3);
                }
                // B fragments + MMAs in quads
#pragma unroll
                for (int ntq = 0; ntq < 2; ntq++) {
                    uint32_t bfr[4][4];
#pragma unroll
                    for (int q = 0; q < 4; q++) {
                        int nt = ntq * 4 + q;
                        uint32_t addr = Bb + (uint32_t)(h * 8192)
                            + SMEM_SWZ((uint32_t)((nt * 8 + r_c) * 128 + (sp * 32 + jo) * 2));
                        LDSM4(bfr[q], addr);
                    }
#pragma unroll
                    for (int q = 0; q < 4; q++) {
#pragma unroll
                        for (int k2 = 0; k2 < 2; k2++) {
                            MMA16816(acc[hh][ntq * 4 + q],
                                     ahi[k2][0], ahi[k2][1], ahi[k2][2], ahi[k2][3],
                                     bfr[q][k2 * 2], bfr[q][k2 * 2 + 1]);
                        }
                    }
                }
            }
        }
        __syncthreads();
    }

    // ---- epilogue ----
#pragma unroll
    for (int r = 0; r < 2; r++)
#pragma unroll
        for (int hh = 0; hh < 2; hh++) {
            den[r][hh] += __shfl_xor_sync(0xFFFFFFFFu, den[r][hh], 1);
            den[r][hh] += __shfl_xor_sync(0xFFFFFFFFu, den[r][hh], 2);
        }
    if (tg == 0) {
        *(float2*)(g_denP + ((size_t)js * NN + iA)     * NHEAD + hpair * 2) =
            make_float2(den[0][0], den[0][1]);
        *(float2*)(g_denP + ((size_t)js * NN + iA + 8) * NHEAD + hpair * 2) =
            make_float2(den[1][0], den[1][1]);
    }
#pragma unroll
    for (int hh = 0; hh < 2; hh++) {
        const int h = hpair * 2 + hh;
#pragma unroll
        for (int nt = 0; nt < 8; nt++) {
            const int c0 = h * 64 + nt * 8 + tg * 2;
            *(float2*)(g_outP + ((size_t)js * NN + iA)     * COLS + c0) =
                make_float2(acc[hh][nt][0], acc[hh][nt][1]);
            *(float2*)(g_outP + ((size_t)js * NN + iA + 8) * COLS + c0) =
                make_float2(acc[hh][nt][2], acc[hh][nt][3]);
        }
    }
}

// ---------------------------------------------------------------------------
// Kernel 3: combine j-split partials
// ---------------------------------------------------------------------------
__global__ __launch_bounds__(256) void k_comb(float* __restrict__ out)
{
    const int idx = blockIdx.x * 256 + threadIdx.x;   // float4 index over NN*64
    const int i  = idx >> 6;
    const int c4 = idx & 63;
    const int h  = c4 >> 4;

    float4 s = make_float4(0.f, 0.f, 0.f, 0.f);
    float d = 0.f;
#pragma unroll
    for (int js = 0; js < JS; js++) {
        float4 p = ((const float4*)g_outP)[((size_t)js * NN + i) * 64 + c4];
        s.x += p.x; s.y += p.y; s.z += p.z; s.w += p.w;
        d += g_denP[((size_t)js * NN + i) * NHEAD + h];
    }
    float inv = 1.0f / d;
    ((float4*)out)[idx] = make_float4(s.x * inv, s.y * inv, s.z * inv, s.w * inv);
}

// ---------------------------------------------------------------------------
extern "C" void kernel_launch(void* const* d_in, const int* in_sizes, int n_in,
                              void* d_out, int out_size)
{
    const float* hmat = (const float*)d_in[0];   // [8192, 256] f32
    const int*   adj  = (const int*)  d_in[1];   // [8192, 8192] i32
    const float* W    = (const float*)d_in[2];   // [4, 256, 64] f32
    const float* a    = (const float*)d_in[3];   // [128, 1] f32
    float* out = (float*)d_out;                  // [8192, 256] f32

    cudaFuncSetAttribute(k_attn, cudaFuncAttributeMaxDynamicSharedMemorySize, SMEM_REQ);

    k_gemm  <<<NN / 16, 256>>>(hmat, W);
    k_scores<<<(NN * NHEAD) / 8, 256>>>(a);
    k_attn  <<<(NN / TI) * JS, 256, SMEM_REQ>>>(adj);
    k_comb  <<<(NN * 64) / 256, 256>>>(out);
}

// round 8
// speedup vs baseline: 8.2659x; 1.0216x over previous
#include <cuda_runtime.h>
#include <cuda_fp16.h>
#include <cstdint>

// Problem constants
#define NN       8192
#define IN_DIM   256
#define NHEAD    4
#define HDIM     64
#define COLS     256   // NHEAD*HDIM

// attention tiling
#define TI   64                    // rows per block
#define TJ   64                    // j per chunk (K)
#define JS   16                    // j-splits
#define JCH  ((NN / JS) / TJ)      // 8 chunks per block

// smem byte offsets (from 1024-aligned base) — 3-deep ring
#define OFF_B     0u               // 3 bufs x 32768 (256 c-rows x 64 j fp16, SW128)
#define OFF_EFS   98304u           // 3 bufs x 2048  ([h][64 j] float2 {E2,F2})
#define OFF_S1    104448u          // 2048 (64 i x 4 h float2 {E1,F1})
#define SMEM_REQ  (106496u + 1024u)

#define SMEM_SWZ(off) ((off) ^ (((off) >> 3) & 0x70u))

// ---------------- PTX helpers ----------------
__device__ __forceinline__ uint32_t smem_u32(const void* p) {
    uint32_t a;
    asm("{ .reg .u64 t; cvta.to.shared.u64 t, %1; cvt.u32.u64 %0, t; }" : "=r"(a) : "l"(p));
    return a;
}
#define PACK2(out, lo, hi) \
    asm("mov.b64 %0, {%1, %2};" : "=l"(out) : "f"(lo), "f"(hi))
#define UNPACK2(lo, hi, in) \
    asm("mov.b64 {%0, %1}, %2;" : "=f"(lo), "=f"(hi) : "l"(in))
#define FMA2(d, a, b, c) \
    asm("fma.rn.f32x2 %0, %1, %2, %3;" : "=l"(d) : "l"(a), "l"(b), "l"(c))
// pack two f32 -> f16x2 (lo in low half)
#define CVT_F16X2(r, lo, hi) \
    asm("cvt.rn.f16x2.f32 %0, %1, %2;" : "=r"(r) : "f"(hi), "f"(lo))

#define CP_ASYNC16(dst, src) \
    asm volatile("cp.async.cg.shared.global [%0], [%1], 16;" :: "r"(dst), "l"(src))
#define CP_ASYNC8(dst, src) \
    asm volatile("cp.async.ca.shared.global [%0], [%1], 8;" :: "r"(dst), "l"(src))
#define CP_COMMIT() asm volatile("cp.async.commit_group;" ::: "memory")
#define CP_WAIT(n)  asm volatile("cp.async.wait_group %0;" :: "n"(n) : "memory")

#define LDSM4(r, addr) \
    asm volatile("ldmatrix.sync.aligned.m8n8.x4.shared.b16 {%0,%1,%2,%3}, [%4];" \
        : "=r"((r)[0]), "=r"((r)[1]), "=r"((r)[2]), "=r"((r)[3]) : "r"(addr))

#define MMA16816(d, a0, a1, a2, a3, b0, b1) \
    asm volatile("mma.sync.aligned.m16n8k16.row.col.f32.f16.f16.f32 " \
        "{%0,%1,%2,%3}, {%4,%5,%6,%7}, {%8,%9}, {%0,%1,%2,%3};" \
        : "+f"((d)[0]), "+f"((d)[1]), "+f"((d)[2]), "+f"((d)[3]) \
        : "r"(a0), "r"(a1), "r"(a2), "r"(a3), "r"(b0), "r"(b1))

// masked-max weight: max(E1*E2, F1*F2) & sext(bit)
__device__ __forceinline__ float wmax_masked(float E1, float F1, float E2, float F2,
                                             uint32_t m, int k) {
    float v = fmaxf(E1 * E2, F1 * F2);
    return __int_as_float(__float_as_int(v) & (-(int)((m >> k) & 1u)));
}

// ---------------- scratch globals ----------------
__device__ float   g_Wht[NN * COLS];            // Wh fp32 [n][c] (for scores)
__device__ __half  g_WTf16[COLS * NN];          // Wh^T fp16 [c][j]  (4 MB)
__device__ float2  g_S12[NN * NHEAD];           // {e^s1, e^{.2 s1}}
__device__ float2  g_EFS2[NN * NHEAD];          // {e^s2, e^{.2 s2}}
__device__ float   g_outP[(size_t)JS * NN * COLS];
__device__ float   g_denP[(size_t)JS * NN * NHEAD];

// ---------------------------------------------------------------------------
// Kernel 1: Wh = h @ W ; also emit fp16 Wh^T plane.
// ---------------------------------------------------------------------------
__global__ __launch_bounds__(256) void k_gemm(const float* __restrict__ hmat,
                                              const float* __restrict__ W)
{
    __shared__ __align__(16) float hsT[IN_DIM][18];
    const int n0 = blockIdx.x * 16;
    const int t  = threadIdx.x;

    for (int q = t; q < 1024; q += 256) {
        int row = q >> 6, kq = q & 63;
        float4 v = *(const float4*)(hmat + (n0 + row) * IN_DIM + kq * 4);
        hsT[kq * 4 + 0][row] = v.x;
        hsT[kq * 4 + 1][row] = v.y;
        hsT[kq * 4 + 2][row] = v.z;
        hsT[kq * 4 + 3][row] = v.w;
    }
    __syncthreads();

    const int c = t;
    const int head = c >> 6, d = c & 63;
    const float* Wp = W + head * (IN_DIM * HDIM) + d;

    unsigned long long acc[8];
#pragma unroll
    for (int rp = 0; rp < 8; rp++) acc[rp] = 0ull;

#pragma unroll 4
    for (int k = 0; k < IN_DIM; k++) {
        float wv = Wp[k * HDIM];
        unsigned long long ws;
        PACK2(ws, wv, wv);
#pragma unroll
        for (int rp = 0; rp < 8; rp++) {
            unsigned long long hv = *(const unsigned long long*)&hsT[k][rp * 2];
            FMA2(acc[rp], hv, ws, acc[rp]);
        }
    }

    float val[16];
#pragma unroll
    for (int rp = 0; rp < 8; rp++) {
        UNPACK2(val[2 * rp], val[2 * rp + 1], acc[rp]);
        g_Wht[(n0 + 2 * rp + 0) * COLS + c] = val[2 * rp];
        g_Wht[(n0 + 2 * rp + 1) * COLS + c] = val[2 * rp + 1];
    }
    uint32_t hp[8];
#pragma unroll
    for (int q = 0; q < 8; q++) CVT_F16X2(hp[q], val[2 * q], val[2 * q + 1]);
    uint4* pd = (uint4*)(g_WTf16 + (size_t)c * NN + n0);
    pd[0] = make_uint4(hp[0], hp[1], hp[2], hp[3]);
    pd[1] = make_uint4(hp[4], hp[5], hp[6], hp[7]);
}

// ---------------------------------------------------------------------------
// Kernel 1b: scores + exp precompute ({E, F} pairs only)
// ---------------------------------------------------------------------------
__global__ __launch_bounds__(256) void k_scores(const float* __restrict__ a)
{
    const int gw   = (blockIdx.x * blockDim.x + threadIdx.x) >> 5;
    const int lane = threadIdx.x & 31;
    const int n = gw >> 2, head = gw & 3;

    float2 wv = *(const float2*)(g_Wht + n * COLS + head * HDIM + lane * 2);
    float a1x = a[lane * 2],      a1y = a[lane * 2 + 1];
    float a2x = a[64 + lane * 2], a2y = a[64 + lane * 2 + 1];
    float p1 = wv.x * a1x + wv.y * a1y;
    float p2 = wv.x * a2x + wv.y * a2y;
#pragma unroll
    for (int off = 16; off > 0; off >>= 1) {
        p1 += __shfl_xor_sync(0xFFFFFFFFu, p1, off);
        p2 += __shfl_xor_sync(0xFFFFFFFFu, p2, off);
    }
    if (lane == 0) {
        g_S12 [n * NHEAD + head] = make_float2(expf(p1), expf(0.2f * p1));
        g_EFS2[n * NHEAD + head] = make_float2(expf(p2), expf(0.2f * p2));
    }
}

// ---------------------------------------------------------------------------
// Kernel 2: HMMA attention aggregation. grid = (NN/TI)*JS = 2048, 256 thr,
// 2 blocks/SM. Warp = 16 rows x 2 heads. 3-deep cp.async ring -> ONE barrier
// per chunk; MMA order k2-outer for dependency distance 4.
// ---------------------------------------------------------------------------
__global__ __launch_bounds__(256, 2) void k_attn(const int* __restrict__ adj)
{
    extern __shared__ __align__(16) char dsm[];
    const uint32_t sb = smem_u32(dsm);
    const uint32_t ab = (sb + 1023u) & ~1023u;
    char* abp = dsm + (ab - sb);

    const int t    = threadIdx.x;
    const int wid  = t >> 5;
    const int lane = t & 31;
    const int g    = lane >> 2;
    const int tg   = lane & 3;
    const int rg    = wid >> 1;        // rowgroup 0..3
    const int hpair = wid & 1;         // heads hpair*2, hpair*2+1
    const int bx = blockIdx.x;
    const int js    = bx & (JS - 1);
    const int itile = bx >> 4;
    const int i0     = itile * TI;
    const int j0base = js * (NN / JS);

    const int ilA = rg * 16 + g;           // local row A
    const int iA  = i0 + ilA;              // global row A (B = +8)

    // stage S1 {E1,F1} once: 64 i x 4 h float2
    *(float2*)(abp + OFF_S1 + t * 8) = g_S12[i0 * NHEAD + t];

    auto stage = [&](int buf, int j0) {
        // B: 256 c-rows x 64 j fp16; 16B granules, swizzled
#pragma unroll
        for (int v = 0; v < 8; v++) {
            int idx = v * 256 + t;
            int row = idx >> 3, u = idx & 7;
            const __half* src = g_WTf16 + (size_t)row * NN + j0 + u * 8;
            uint32_t dst = ab + OFF_B + buf * 32768 + SMEM_SWZ((uint32_t)(row * 128 + u * 16));
            CP_ASYNC16(dst, src);
        }
        // EFS: transpose to [h][64 j] float2
        {
            int h = t & 3, jl = t >> 2;
            const float2* src = g_EFS2 + (j0 + jl) * NHEAD + h;
            uint32_t dst = ab + OFF_EFS + buf * 2048 + (uint32_t)(h * 64 + jl) * 8;
            CP_ASYNC8(dst, src);
        }
    };

    stage(0, j0base);
    CP_COMMIT();
    stage(1, j0base + TJ);
    CP_COMMIT();

    float acc[2][8][4];
#pragma unroll
    for (int hh = 0; hh < 2; hh++)
#pragma unroll
        for (int nt = 0; nt < 8; nt++)
#pragma unroll
            for (int q = 0; q < 4; q++) acc[hh][nt][q] = 0.0f;
    float den[2][2];
    den[0][0] = den[0][1] = den[1][0] = den[1][1] = 0.0f;

    for (int ch = 0; ch < JCH; ch++) {
        const int buf = ch % 3;
        const int j0  = j0base + ch * TJ;

        // adj bitmasks for this chunk (overlap DRAM latency with cp waits)
        uint32_t mA = 0, mB = 0;
        {
            const int* ap = adj + (size_t)iA * NN + j0 + tg * 2;
#pragma unroll
            for (int s = 0; s < 4; s++) {
                int2 a0 = *(const int2*)(ap + s * 16);
                int2 a1 = *(const int2*)(ap + s * 16 + 8);
                int2 b0 = *(const int2*)(ap + (size_t)8 * NN + s * 16);
                int2 b1 = *(const int2*)(ap + (size_t)8 * NN + s * 16 + 8);
                mA |= (uint32_t)(a0.x & 1) << (s * 4) | (uint32_t)(a0.y & 1) << (s * 4 + 1)
                    | (uint32_t)(a1.x & 1) << (s * 4 + 2) | (uint32_t)(a1.y & 1) << (s * 4 + 3);
                mB |= (uint32_t)(b0.x & 1) << (s * 4) | (uint32_t)(b0.y & 1) << (s * 4 + 1)
                    | (uint32_t)(b1.x & 1) << (s * 4 + 2) | (uint32_t)(b1.y & 1) << (s * 4 + 3);
            }
        }

        // wait for this chunk's buffer; newest pending group may stay in flight
        if (ch < JCH - 1) CP_WAIT(1); else CP_WAIT(0);
        __syncthreads();   // ONE barrier per chunk: copies visible + ring-slot reuse safe

        // stage chunk ch+2 into the slot last read at chunk ch-1
        if (ch + 2 < JCH) {
            stage((ch + 2) % 3, j0 + 2 * TJ);
            CP_COMMIT();
        }

        const uint32_t Eb = ab + OFF_EFS + buf * 2048;
        const uint32_t Bb = ab + OFF_B + buf * 32768;

        const int r_c = lane & 7;
        const int jo  = ((lane >> 3) & 3) * 8;   // 0,8,16,24

#pragma unroll
        for (int hh = 0; hh < 2; hh++) {
            const int h = hpair * 2 + hh;
            float2 efA = *(const float2*)(abp + OFF_S1 + ((ilA) * 4 + h) * 8);
            float2 efB = *(const float2*)(abp + OFF_S1 + ((ilA + 8) * 4 + h) * 8);

#pragma unroll
            for (int sp = 0; sp < 2; sp++) {
                // A fragments for 2 ksteps — flat ILP, no branches/selects
                uint32_t ahi[2][4];
#pragma unroll
                for (int k2 = 0; k2 < 2; k2++) {
                    const int s  = sp * 2 + k2;
                    const int jj = s * 16 + tg * 2;
                    float4 p01 = *(const float4*)(abp + (Eb - ab) + (uint32_t)(h * 64 + jj) * 8);
                    float4 p89 = *(const float4*)(abp + (Eb - ab) + (uint32_t)(h * 64 + jj + 8) * 8);

                    float wA0 = wmax_masked(efA.x, efA.y, p01.x, p01.y, mA, s * 4 + 0);
                    float wA1 = wmax_masked(efA.x, efA.y, p01.z, p01.w, mA, s * 4 + 1);
                    float wA2 = wmax_masked(efA.x, efA.y, p89.x, p89.y, mA, s * 4 + 2);
                    float wA3 = wmax_masked(efA.x, efA.y, p89.z, p89.w, mA, s * 4 + 3);
                    float wB0 = wmax_masked(efB.x, efB.y, p01.x, p01.y, mB, s * 4 + 0);
                    float wB1 = wmax_masked(efB.x, efB.y, p01.z, p01.w, mB, s * 4 + 1);
                    float wB2 = wmax_masked(efB.x, efB.y, p89.x, p89.y, mB, s * 4 + 2);
                    float wB3 = wmax_masked(efB.x, efB.y, p89.z, p89.w, mB, s * 4 + 3);

                    den[0][hh] += (wA0 + wA1) + (wA2 + wA3);
                    den[1][hh] += (wB0 + wB1) + (wB2 + wB3);

                    CVT_F16X2(ahi[k2][0], wA0, wA1);
                    CVT_F16X2(ahi[k2][1], wB0, wB1);
                    CVT_F16X2(ahi[k2][2], wA2, wA3);
                    CVT_F16X2(ahi[k2][3], wB2, wB3);
                }
                // B fragments + MMAs in quads; k2-outer => dependency distance 4
#pragma unroll
                for (int ntq = 0; ntq < 2; ntq++) {
                    uint32_t bfr[4][4];
#pragma unroll
                    for (int q = 0; q < 4; q++) {
                        int nt = ntq * 4 + q;
                        uint32_t addr = Bb + (uint32_t)(h * 8192)
                            + SMEM_SWZ((uint32_t)((nt * 8 + r_c) * 128 + (sp * 32 + jo) * 2));
                        LDSM4(bfr[q], addr);
                    }
#pragma unroll
                    for (int k2 = 0; k2 < 2; k2++) {
#pragma unroll
                        for (int q = 0; q < 4; q++) {
                            MMA16816(acc[hh][ntq * 4 + q],
                                     ahi[k2][0], ahi[k2][1], ahi[k2][2], ahi[k2][3],
                                     bfr[q][k2 * 2], bfr[q][k2 * 2 + 1]);
                        }
                    }
                }
            }
        }
        // no trailing barrier: ring slot (ch+2)%3 staged above is safe, and
        // next iteration's barrier protects slot (ch+3)%3 reuse.
    }

    // ---- epilogue ----
#pragma unroll
    for (int r = 0; r < 2; r++)
#pragma unroll
        for (int hh = 0; hh < 2; hh++) {
            den[r][hh] += __shfl_xor_sync(0xFFFFFFFFu, den[r][hh], 1);
            den[r][hh] += __shfl_xor_sync(0xFFFFFFFFu, den[r][hh], 2);
        }
    if (tg == 0) {
        *(float2*)(g_denP + ((size_t)js * NN + iA)     * NHEAD + hpair * 2) =
            make_float2(den[0][0], den[0][1]);
        *(float2*)(g_denP + ((size_t)js * NN + iA + 8) * NHEAD + hpair * 2) =
            make_float2(den[1][0], den[1][1]);
    }
#pragma unroll
    for (int hh = 0; hh < 2; hh++) {
        const int h = hpair * 2 + hh;
#pragma unroll
        for (int nt = 0; nt < 8; nt++) {
            const int c0 = h * 64 + nt * 8 + tg * 2;
            *(float2*)(g_outP + ((size_t)js * NN + iA)     * COLS + c0) =
                make_float2(acc[hh][nt][0], acc[hh][nt][1]);
            *(float2*)(g_outP + ((size_t)js * NN + iA + 8) * COLS + c0) =
                make_float2(acc[hh][nt][2], acc[hh][nt][3]);
        }
    }
}

// ---------------------------------------------------------------------------
// Kernel 3: combine j-split partials
// ---------------------------------------------------------------------------
__global__ __launch_bounds__(256) void k_comb(float* __restrict__ out)
{
    const int idx = blockIdx.x * 256 + threadIdx.x;   // float4 index over NN*64
    const int i  = idx >> 6;
    const int c4 = idx & 63;
    const int h  = c4 >> 4;

    float4 s = make_float4(0.f, 0.f, 0.f, 0.f);
    float d = 0.f;
#pragma unroll
    for (int js = 0; js < JS; js++) {
        float4 p = ((const float4*)g_outP)[((size_t)js * NN + i) * 64 + c4];
        s.x += p.x; s.y += p.y; s.z += p.z; s.w += p.w;
        d += g_denP[((size_t)js * NN + i) * NHEAD + h];
    }
    float inv = 1.0f / d;
    ((float4*)out)[idx] = make_float4(s.x * inv, s.y * inv, s.z * inv, s.w * inv);
}

// ---------------------------------------------------------------------------
extern "C" void kernel_launch(void* const* d_in, const int* in_sizes, int n_in,
                              void* d_out, int out_size)
{
    const float* hmat = (const float*)d_in[0];   // [8192, 256] f32
    const int*   adj  = (const int*)  d_in[1];   // [8192, 8192] i32
    const float* W    = (const float*)d_in[2];   // [4, 256, 64] f32
    const float* a    = (const float*)d_in[3];   // [128, 1] f32
    float* out = (float*)d_out;                  // [8192, 256] f32

    cudaFuncSetAttribute(k_attn, cudaFuncAttributeMaxDynamicSharedMemorySize, SMEM_REQ);

    k_gemm  <<<NN / 16, 256>>>(hmat, W);
    k_scores<<<(NN * NHEAD) / 8, 256>>>(a);
    k_attn  <<<(NN / TI) * JS, 256, SMEM_REQ>>>(adj);
    k_comb  <<<(NN * 64) / 256, 256>>>(out);
}

// round 9
// speedup vs baseline: 8.8683x; 1.0729x over previous
#include <cuda_runtime.h>
#include <cuda_fp16.h>
#include <cstdint>

// Problem constants
#define NN       8192
#define IN_DIM   256
#define NHEAD    4
#define HDIM     64
#define COLS     256   // NHEAD*HDIM

// attention tiling
#define TI   64                    // rows per block
#define TJ   64                    // j per chunk (K)
#define JS   8                     // j-splits
#define JCH  ((NN / JS) / TJ)      // 16 chunks per block

// smem byte offsets — 3-deep ring
#define OFF_B     0u               // 3 bufs x 32768 (256 c-rows x 64 j fp16, SW128)
#define OFF_EFS   98304u           // 3 bufs x 2048  ([h][64 j] float2 {E2,F2})
#define SMEM_REQ  (104448u + 1024u)

#define SMEM_SWZ(off) ((off) ^ (((off) >> 3) & 0x70u))

// ---------------- PTX helpers ----------------
__device__ __forceinline__ uint32_t smem_u32(const void* p) {
    uint32_t a;
    asm("{ .reg .u64 t; cvta.to.shared.u64 t, %1; cvt.u32.u64 %0, t; }" : "=r"(a) : "l"(p));
    return a;
}
#define PACK2(out, lo, hi) \
    asm("mov.b64 %0, {%1, %2};" : "=l"(out) : "f"(lo), "f"(hi))
#define UNPACK2(lo, hi, in) \
    asm("mov.b64 {%0, %1}, %2;" : "=f"(lo), "=f"(hi) : "l"(in))
#define FMA2(d, a, b, c) \
    asm("fma.rn.f32x2 %0, %1, %2, %3;" : "=l"(d) : "l"(a), "l"(b), "l"(c))
#define MUL2(d, a, b) \
    asm("mul.rn.f32x2 %0, %1, %2;" : "=l"(d) : "l"(a), "l"(b))
// pack two f32 -> f16x2 (lo in low half)
#define CVT_F16X2(r, lo, hi) \
    asm("cvt.rn.f16x2.f32 %0, %1, %2;" : "=r"(r) : "f"(hi), "f"(lo))

#define CP_ASYNC16(dst, src) \
    asm volatile("cp.async.cg.shared.global [%0], [%1], 16;" :: "r"(dst), "l"(src))
#define CP_ASYNC8(dst, src) \
    asm volatile("cp.async.ca.shared.global [%0], [%1], 8;" :: "r"(dst), "l"(src))
#define CP_COMMIT() asm volatile("cp.async.commit_group;" ::: "memory")
#define CP_WAIT(n)  asm volatile("cp.async.wait_group %0;" :: "n"(n) : "memory")

#define LDSM2(r0, r1, addr) \
    asm volatile("ldmatrix.sync.aligned.m8n8.x2.shared.b16 {%0,%1}, [%2];" \
        : "=r"(r0), "=r"(r1) : "r"(addr))

#define MMA16816(d, a0, a1, a2, a3, b0, b1) \
    asm volatile("mma.sync.aligned.m16n8k16.row.col.f32.f16.f16.f32 " \
        "{%0,%1,%2,%3}, {%4,%5,%6,%7}, {%8,%9}, {%0,%1,%2,%3};" \
        : "+f"((d)[0]), "+f"((d)[1]), "+f"((d)[2]), "+f"((d)[3]) \
        : "r"(a0), "r"(a1), "r"(a2), "r"(a3), "r"(b0), "r"(b1))

// max(E1*E2, F1*F2) from packed product, then bit-masked select
__device__ __forceinline__ float wmax_sel(unsigned long long s1p, unsigned long long ef,
                                          uint32_t wrd, uint32_t bm) {
    unsigned long long prod;
    MUL2(prod, s1p, ef);
    float lo, hi;
    UNPACK2(lo, hi, prod);
    float v = fmaxf(lo, hi);
    return (wrd & bm) ? v : 0.0f;
}

// ---------------- scratch globals ----------------
__device__ float    g_Wht[NN * COLS];            // Wh fp32 [n][c] (for scores)
__device__ __half   g_WTf16[COLS * NN];          // Wh^T fp16 [c][j]  (4 MB)
__device__ float2   g_S12[NN * NHEAD];           // {e^s1, e^{.2 s1}}
__device__ float2   g_EFS2[NN * NHEAD];          // {e^s2, e^{.2 s2}}
__device__ uint32_t g_adjbits[(size_t)NN * (NN / 32)];   // 8 MB bitmask
__device__ float    g_outP[(size_t)JS * NN * COLS];      // 64 MB
__device__ float    g_denP[(size_t)JS * NN * NHEAD];

// ---------------------------------------------------------------------------
// Kernel 0: pack adj into bitmask. One warp per row; ballot per 32 j.
// ---------------------------------------------------------------------------
__global__ __launch_bounds__(256) void k_pack(const int* __restrict__ adj)
{
    const int row  = blockIdx.x * 8 + (threadIdx.x >> 5);
    const int lane = threadIdx.x & 31;
    const int* rp = adj + (size_t)row * NN;
    uint32_t* op = g_adjbits + (size_t)row * (NN / 32);
#pragma unroll 4
    for (int w = 0; w < NN / 32; w++) {
        int v = rp[w * 32 + lane];
        uint32_t bits = __ballot_sync(0xFFFFFFFFu, v != 0);
        if (lane == 0) op[w] = bits;
    }
}

// ---------------------------------------------------------------------------
// Kernel 1: Wh = h @ W ; also emit fp16 Wh^T plane.
// ---------------------------------------------------------------------------
__global__ __launch_bounds__(256) void k_gemm(const float* __restrict__ hmat,
                                              const float* __restrict__ W)
{
    __shared__ __align__(16) float hsT[IN_DIM][18];
    const int n0 = blockIdx.x * 16;
    const int t  = threadIdx.x;

    for (int q = t; q < 1024; q += 256) {
        int row = q >> 6, kq = q & 63;
        float4 v = *(const float4*)(hmat + (n0 + row) * IN_DIM + kq * 4);
        hsT[kq * 4 + 0][row] = v.x;
        hsT[kq * 4 + 1][row] = v.y;
        hsT[kq * 4 + 2][row] = v.z;
        hsT[kq * 4 + 3][row] = v.w;
    }
    __syncthreads();

    const int c = t;
    const int head = c >> 6, d = c & 63;
    const float* Wp = W + head * (IN_DIM * HDIM) + d;

    unsigned long long acc[8];
#pragma unroll
    for (int rp = 0; rp < 8; rp++) acc[rp] = 0ull;

#pragma unroll 4
    for (int k = 0; k < IN_DIM; k++) {
        float wv = Wp[k * HDIM];
        unsigned long long ws;
        PACK2(ws, wv, wv);
#pragma unroll
        for (int rp = 0; rp < 8; rp++) {
            unsigned long long hv = *(const unsigned long long*)&hsT[k][rp * 2];
            FMA2(acc[rp], hv, ws, acc[rp]);
        }
    }

    float val[16];
#pragma unroll
    for (int rp = 0; rp < 8; rp++) {
        UNPACK2(val[2 * rp], val[2 * rp + 1], acc[rp]);
        g_Wht[(n0 + 2 * rp + 0) * COLS + c] = val[2 * rp];
        g_Wht[(n0 + 2 * rp + 1) * COLS + c] = val[2 * rp + 1];
    }
    uint32_t hp[8];
#pragma unroll
    for (int q = 0; q < 8; q++) CVT_F16X2(hp[q], val[2 * q], val[2 * q + 1]);
    uint4* pd = (uint4*)(g_WTf16 + (size_t)c * NN + n0);
    pd[0] = make_uint4(hp[0], hp[1], hp[2], hp[3]);
    pd[1] = make_uint4(hp[4], hp[5], hp[6], hp[7]);
}

// ---------------------------------------------------------------------------
// Kernel 1b: scores + exp precompute ({E, F} pairs only)
// ---------------------------------------------------------------------------
__global__ __launch_bounds__(256) void k_scores(const float* __restrict__ a)
{
    const int gw   = (blockIdx.x * blockDim.x + threadIdx.x) >> 5;
    const int lane = threadIdx.x & 31;
    const int n = gw >> 2, head = gw & 3;

    float2 wv = *(const float2*)(g_Wht + n * COLS + head * HDIM + lane * 2);
    float a1x = a[lane * 2],      a1y = a[lane * 2 + 1];
    float a2x = a[64 + lane * 2], a2y = a[64 + lane * 2 + 1];
    float p1 = wv.x * a1x + wv.y * a1y;
    float p2 = wv.x * a2x + wv.y * a2y;
#pragma unroll
    for (int off = 16; off > 0; off >>= 1) {
        p1 += __shfl_xor_sync(0xFFFFFFFFu, p1, off);
        p2 += __shfl_xor_sync(0xFFFFFFFFu, p2, off);
    }
    if (lane == 0) {
        g_S12 [n * NHEAD + head] = make_float2(expf(p1), expf(0.2f * p1));
        g_EFS2[n * NHEAD + head] = make_float2(expf(p2), expf(0.2f * p2));
    }
}

// ---------------------------------------------------------------------------
// Kernel 2: HMMA attention aggregation. grid = (NN/TI)*JS = 1024, 256 thr,
// 2 blocks/SM. Warp = 32 rows x 1 head (rg = wid>>2, h = wid&3).
// Bitmask adj, packed-mul weight phase, ldmatrix.x2 B fragments.
// ---------------------------------------------------------------------------
__global__ __launch_bounds__(256, 2) void k_attn()
{
    extern __shared__ __align__(16) char dsm[];
    const uint32_t sb = smem_u32(dsm);
    const uint32_t ab = (sb + 1023u) & ~1023u;
    char* abp = dsm + (ab - sb);

    const int t    = threadIdx.x;
    const int wid  = t >> 5;
    const int lane = t & 31;
    const int g    = lane >> 2;
    const int tg   = lane & 3;
    const int rg   = wid >> 2;         // rowgroup 0..1 (32 rows each)
    const int h    = wid & 3;          // head
    const int bx = blockIdx.x;
    const int js    = bx & (JS - 1);
    const int itile = bx >> 3;         // JS = 8
    const int i0     = itile * TI;
    const int j0base = js * (NN / JS);

    const int rbase = i0 + rg * 32 + g;    // rows rbase + {0,8,16,24}

    // hoisted per-row score pairs {E1,F1} (packed u64) and adj-bit base ptrs
    unsigned long long s1p[4];
    const uint32_t* bitp[4];
#pragma unroll
    for (int ri = 0; ri < 4; ri++) {
        const int row = rbase + ri * 8;
        s1p[ri]  = *(const unsigned long long*)(g_S12 + row * NHEAD + h);
        bitp[ri] = g_adjbits + (size_t)row * (NN / 32);
    }
    // bit-select masks: bm[delta] for j = s*16 + tg*2 + {0,1,8,9}, s even; <<16 for s odd
    uint32_t bm[8];
    {
        uint32_t b0 = 1u << (tg * 2);
        bm[0] = b0;        bm[1] = b0 << 1;  bm[2] = b0 << 8;  bm[3] = b0 << 9;
        bm[4] = b0 << 16;  bm[5] = b0 << 17; bm[6] = b0 << 24; bm[7] = b0 << 25;
    }

    auto stage = [&](int buf, int j0) {
#pragma unroll
        for (int v = 0; v < 8; v++) {
            int idx = v * 256 + t;
            int row = idx >> 3, u = idx & 7;
            const __half* src = g_WTf16 + (size_t)row * NN + j0 + u * 8;
            uint32_t dst = ab + OFF_B + buf * 32768 + SMEM_SWZ((uint32_t)(row * 128 + u * 16));
            CP_ASYNC16(dst, src);
        }
        {
            int hh = t & 3, jl = t >> 2;
            const float2* src = g_EFS2 + (j0 + jl) * NHEAD + hh;
            uint32_t dst = ab + OFF_EFS + buf * 2048 + (uint32_t)(hh * 64 + jl) * 8;
            CP_ASYNC8(dst, src);
        }
    };

    stage(0, j0base);
    CP_COMMIT();
    stage(1, j0base + TJ);
    CP_COMMIT();

    float acc[2][8][4];
#pragma unroll
    for (int mt = 0; mt < 2; mt++)
#pragma unroll
        for (int nt = 0; nt < 8; nt++)
#pragma unroll
            for (int q = 0; q < 4; q++) acc[mt][nt][q] = 0.0f;
    float den[4] = {0.f, 0.f, 0.f, 0.f};

    for (int ch = 0; ch < JCH; ch++) {
        const int buf = ch % 3;
        const int j0  = j0base + ch * TJ;

        // adj bit-words for this chunk: 2 words per row, 4 rows (L2-resident)
        uint32_t wds[4][2];
        {
            const int w0 = j0 >> 5;
#pragma unroll
            for (int ri = 0; ri < 4; ri++) {
                wds[ri][0] = bitp[ri][w0];
                wds[ri][1] = bitp[ri][w0 + 1];
            }
        }

        if (ch < JCH - 1) CP_WAIT(1); else CP_WAIT(0);
        __syncthreads();

        if (ch + 2 < JCH) {
            stage((ch + 2) % 3, j0 + 2 * TJ);
            CP_COMMIT();
        }

        const uint32_t Eoff = OFF_EFS + buf * 2048;
        const uint32_t Bb = ab + OFF_B + buf * 32768;
        const int r_c = lane & 7;
        const int jo2 = ((lane >> 3) & 1) * 8;

#pragma unroll
        for (int sp = 0; sp < 2; sp++) {
#pragma unroll
            for (int k2 = 0; k2 < 2; k2++) {
                const int s  = sp * 2 + k2;
                const int jj = s * 16 + tg * 2;
                const int w  = s >> 1;           // word select
                const int ms = (s & 1) * 4;      // mask bank select

                ulonglong2 e01 = *(const ulonglong2*)(abp + Eoff + (uint32_t)(h * 64 + jj) * 8);
                ulonglong2 e89 = *(const ulonglong2*)(abp + Eoff + (uint32_t)(h * 64 + jj + 8) * 8);

                // A fragments for both m-tiles: rows {g, g+8} (mt0), {g+16, g+24} (mt1)
                uint32_t amt[2][4];
#pragma unroll
                for (int mt = 0; mt < 2; mt++) {
#pragma unroll
                    for (int rr = 0; rr < 2; rr++) {
                        const int ri = mt * 2 + rr;
                        float wa = wmax_sel(s1p[ri], e01.x, wds[ri][w], bm[ms + 0]);
                        float wb = wmax_sel(s1p[ri], e01.y, wds[ri][w], bm[ms + 1]);
                        float wc = wmax_sel(s1p[ri], e89.x, wds[ri][w], bm[ms + 2]);
                        float wd = wmax_sel(s1p[ri], e89.y, wds[ri][w], bm[ms + 3]);
                        den[ri] += (wa + wb) + (wc + wd);
                        CVT_F16X2(amt[mt][rr],     wa, wb);   // a0/a1: j (jj,jj+1)
                        CVT_F16X2(amt[mt][rr + 2], wc, wd);   // a2/a3: j (jj+8,jj+9)
                    }
                }

                // B fragments (x2 per n-tile) + MMAs, 2 quads of 4 n-tiles
#pragma unroll
                for (int ntq = 0; ntq < 2; ntq++) {
                    uint32_t bfr[4][2];
#pragma unroll
                    for (int q = 0; q < 4; q++) {
                        int nt = ntq * 4 + q;
                        uint32_t addr = Bb + (uint32_t)(h * 8192)
                            + SMEM_SWZ((uint32_t)((nt * 8 + r_c) * 128
                                                  + (sp * 32 + k2 * 16 + jo2) * 2));
                        LDSM2(bfr[q][0], bfr[q][1], addr);
                    }
#pragma unroll
                    for (int mt = 0; mt < 2; mt++)
#pragma unroll
                        for (int q = 0; q < 4; q++)
                            MMA16816(acc[mt][ntq * 4 + q],
                                     amt[mt][0], amt[mt][1], amt[mt][2], amt[mt][3],
                                     bfr[q][0], bfr[q][1]);
                }
            }
        }
    }

    // ---- epilogue ----
#pragma unroll
    for (int ri = 0; ri < 4; ri++) {
        den[ri] += __shfl_xor_sync(0xFFFFFFFFu, den[ri], 1);
        den[ri] += __shfl_xor_sync(0xFFFFFFFFu, den[ri], 2);
    }
    if (tg == 0) {
#pragma unroll
        for (int ri = 0; ri < 4; ri++)
            g_denP[((size_t)js * NN + rbase + ri * 8) * NHEAD + h] = den[ri];
    }
#pragma unroll
    for (int mt = 0; mt < 2; mt++) {
        const size_t r0 = (size_t)js * NN + rbase + mt * 16;
#pragma unroll
        for (int nt = 0; nt < 8; nt++) {
            const int c0 = h * 64 + nt * 8 + tg * 2;
            *(float2*)(g_outP + r0 * COLS + c0) =
                make_float2(acc[mt][nt][0], acc[mt][nt][1]);
            *(float2*)(g_outP + (r0 + 8) * COLS + c0) =
                make_float2(acc[mt][nt][2], acc[mt][nt][3]);
        }
    }
}

// ---------------------------------------------------------------------------
// Kernel 3: combine j-split partials
// ---------------------------------------------------------------------------
__global__ __launch_bounds__(256) void k_comb(float* __restrict__ out)
{
    const int idx = blockIdx.x * 256 + threadIdx.x;   // float4 index over NN*64
    const int i  = idx >> 6;
    const int c4 = idx & 63;
    const int h  = c4 >> 4;

    float4 s = make_float4(0.f, 0.f, 0.f, 0.f);
    float d = 0.f;
#pragma unroll
    for (int js = 0; js < JS; js++) {
        float4 p = ((const float4*)g_outP)[((size_t)js * NN + i) * 64 + c4];
        s.x += p.x; s.y += p.y; s.z += p.z; s.w += p.w;
        d += g_denP[((size_t)js * NN + i) * NHEAD + h];
    }
    float inv = 1.0f / d;
    ((float4*)out)[idx] = make_float4(s.x * inv, s.y * inv, s.z * inv, s.w * inv);
}

// ---------------------------------------------------------------------------
extern "C" void kernel_launch(void* const* d_in, const int* in_sizes, int n_in,
                              void* d_out, int out_size)
{
    const float* hmat = (const float*)d_in[0];   // [8192, 256] f32
    const int*   adj  = (const int*)  d_in[1];   // [8192, 8192] i32
    const float* W    = (const float*)d_in[2];   // [4, 256, 64] f32
    const float* a    = (const float*)d_in[3];   // [128, 1] f32
    float* out = (float*)d_out;                  // [8192, 256] f32

    cudaFuncSetAttribute(k_attn, cudaFuncAttributeMaxDynamicSharedMemorySize, SMEM_REQ);

    k_pack  <<<NN / 8, 256>>>(adj);
    k_gemm  <<<NN / 16, 256>>>(hmat, W);
    k_scores<<<(NN * NHEAD) / 8, 256>>>(a);
    k_attn  <<<(NN / TI) * JS, 256, SMEM_REQ>>>();
    k_comb  <<<(NN * 64) / 256, 256>>>(out);
}

// round 10
// speedup vs baseline: 9.3805x; 1.0578x over previous
#include <cuda_runtime.h>
#include <cuda_fp16.h>
#include <cstdint>

// Problem constants
#define NN       8192
#define IN_DIM   256
#define NHEAD    4
#define HDIM     64
#define COLS     256   // NHEAD*HDIM

// attention tiling
#define TI   64                    // rows per block
#define TJ   64                    // j per chunk (K)
#define JS   8                     // j-splits
#define JCH  ((NN / JS) / TJ)      // 16 chunks per block

// smem byte offsets — 3-deep ring
#define OFF_B     0u               // 3 bufs x 32768 (256 c-rows x 64 j fp16, SW128)
#define OFF_EFS   98304u           // 3 bufs x 1024 ([h][plane][32 u32] E/F fp16 pairs)
#define SMEM_REQ  (101376u + 1024u)

#define SMEM_SWZ(off) ((off) ^ (((off) >> 3) & 0x70u))

// ---------------- PTX helpers ----------------
__device__ __forceinline__ uint32_t smem_u32(const void* p) {
    uint32_t a;
    asm("{ .reg .u64 t; cvta.to.shared.u64 t, %1; cvt.u32.u64 %0, t; }" : "=r"(a) : "l"(p));
    return a;
}
#define PACK2(out, lo, hi) \
    asm("mov.b64 %0, {%1, %2};" : "=l"(out) : "f"(lo), "f"(hi))
#define UNPACK2(lo, hi, in) \
    asm("mov.b64 {%0, %1}, %2;" : "=f"(lo), "=f"(hi) : "l"(in))
#define FMA2(d, a, b, c) \
    asm("fma.rn.f32x2 %0, %1, %2, %3;" : "=l"(d) : "l"(a), "l"(b), "l"(c))
// pack two f32 -> f16x2 (lo in low half)
#define CVT_F16X2(r, lo, hi) \
    asm("cvt.rn.f16x2.f32 %0, %1, %2;" : "=r"(r) : "f"(hi), "f"(lo))
#define HMUL2(d, a, b) \
    asm("mul.rn.f16x2 %0, %1, %2;" : "=r"(d) : "r"(a), "r"(b))
#define HMAX2(d, a, b) \
    asm("max.f16x2 %0, %1, %2;" : "=r"(d) : "r"(a), "r"(b))
#define PRMT(d, a, sel) \
    asm("prmt.b32 %0, %1, %2, %3;" : "=r"(d) : "r"(a), "r"(0u), "n"(sel))

#define CP_ASYNC16(dst, src) \
    asm volatile("cp.async.cg.shared.global [%0], [%1], 16;" :: "r"(dst), "l"(src))
#define CP_COMMIT() asm volatile("cp.async.commit_group;" ::: "memory")
#define CP_WAIT(n)  asm volatile("cp.async.wait_group %0;" :: "n"(n) : "memory")

#define LDSM2(r0, r1, addr) \
    asm volatile("ldmatrix.sync.aligned.m8n8.x2.shared.b16 {%0,%1}, [%2];" \
        : "=r"(r0), "=r"(r1) : "r"(addr))

#define MMA16816(d, a0, a1, a2, a3, b0, b1) \
    asm volatile("mma.sync.aligned.m16n8k16.row.col.f32.f16.f16.f32 " \
        "{%0,%1,%2,%3}, {%4,%5,%6,%7}, {%8,%9}, {%0,%1,%2,%3};" \
        : "+f"((d)[0]), "+f"((d)[1]), "+f"((d)[2]), "+f"((d)[3]) \
        : "r"(a0), "r"(a1), "r"(a2), "r"(a3), "r"(b0), "r"(b1))

// ---------------- scratch globals ----------------
__device__ float    g_Wht[NN * COLS];            // Wh fp32 [n][c] (for scores)
__device__ __half   g_WTf16[COLS * NN];          // Wh^T fp16 [c][j]  (4 MB)
__device__ uint32_t g_S16[NN * NHEAD];           // {E1 fp16 low, F1 fp16 high}
__device__ __half   g_E2h[NHEAD * NN];           // e^{s2} fp16, [h][n]
__device__ __half   g_F2h[NHEAD * NN];           // e^{.2 s2} fp16, [h][n]
__device__ uint32_t g_adjS[(size_t)NN * 128 * 4];    // spread bitmask, 16 MB
__device__ float    g_outP[(size_t)JS * NN * COLS];  // 64 MB
__device__ float    g_denP[(size_t)JS * NN * NHEAD];

// ---------------------------------------------------------------------------
// Kernel 0: pack adj into SPREAD bitmask.
// Per (row, chunk64, tg): u32 with bit(s, t) at position 8t+4+s where
// j_local = 16s + tg*2 + {0,1,8,9}[t]. One warp per row; ballot per 32 j.
// ---------------------------------------------------------------------------
__global__ __launch_bounds__(256) void k_pack(const int* __restrict__ adj)
{
    const int row  = blockIdx.x * 8 + (threadIdx.x >> 5);
    const int lane = threadIdx.x & 31;
    const int* rp = adj + (size_t)row * NN;
    uint32_t* op = g_adjS + (size_t)row * 512;
#pragma unroll 2
    for (int c = 0; c < 128; c++) {
        int v0 = rp[c * 64 + lane];
        int v1 = rp[c * 64 + 32 + lane];
        uint32_t lo = __ballot_sync(0xFFFFFFFFu, v0 != 0);
        uint32_t hi = __ballot_sync(0xFFFFFFFFu, v1 != 0);
        if (lane < 4) {
            uint32_t l = lo >> (lane * 2);
            uint32_t hh = hi >> (lane * 2);
            uint32_t o = 0;
            o |= (l & 0x1u) << 4;          // s0 t0 -> 4
            o |= (l & 0x2u) << 11;         // s0 t1 -> 12
            o |= (l & 0x100u) << 12;       // s0 t2 -> 20
            o |= (l & 0x200u) << 19;       // s0 t3 -> 28
            o |= (l >> 11) & 0x20u;        // s1 t0 -> 5
            o |= (l & 0x20000u) >> 4;      // s1 t1 -> 13
            o |= (l & 0x1000000u) >> 3;    // s1 t2 -> 21
            o |= (l & 0x2000000u) << 4;    // s1 t3 -> 29
            o |= (hh & 0x1u) << 6;         // s2 t0 -> 6
            o |= (hh & 0x2u) << 13;        // s2 t1 -> 14
            o |= (hh & 0x100u) << 14;      // s2 t2 -> 22
            o |= (hh & 0x200u) << 21;      // s2 t3 -> 30
            o |= (hh >> 9) & 0x80u;        // s3 t0 -> 7
            o |= (hh & 0x20000u) >> 2;     // s3 t1 -> 15
            o |= (hh & 0x1000000u) >> 1;   // s3 t2 -> 23
            o |= (hh & 0x2000000u) << 6;   // s3 t3 -> 31
            op[c * 4 + lane] = o;
        }
    }
}

// ---------------------------------------------------------------------------
// Kernel 1: Wh = h @ W ; also emit fp16 Wh^T plane.
// ---------------------------------------------------------------------------
__global__ __launch_bounds__(256) void k_gemm(const float* __restrict__ hmat,
                                              const float* __restrict__ W)
{
    __shared__ __align__(16) float hsT[IN_DIM][18];
    const int n0 = blockIdx.x * 16;
    const int t  = threadIdx.x;

    for (int q = t; q < 1024; q += 256) {
        int row = q >> 6, kq = q & 63;
        float4 v = *(const float4*)(hmat + (n0 + row) * IN_DIM + kq * 4);
        hsT[kq * 4 + 0][row] = v.x;
        hsT[kq * 4 + 1][row] = v.y;
        hsT[kq * 4 + 2][row] = v.z;
        hsT[kq * 4 + 3][row] = v.w;
    }
    __syncthreads();

    const int c = t;
    const int head = c >> 6, d = c & 63;
    const float* Wp = W + head * (IN_DIM * HDIM) + d;

    unsigned long long acc[8];
#pragma unroll
    for (int rp = 0; rp < 8; rp++) acc[rp] = 0ull;

#pragma unroll 4
    for (int k = 0; k < IN_DIM; k++) {
        float wv = Wp[k * HDIM];
        unsigned long long ws;
        PACK2(ws, wv, wv);
#pragma unroll
        for (int rp = 0; rp < 8; rp++) {
            unsigned long long hv = *(const unsigned long long*)&hsT[k][rp * 2];
            FMA2(acc[rp], hv, ws, acc[rp]);
        }
    }

    float val[16];
#pragma unroll
    for (int rp = 0; rp < 8; rp++) {
        UNPACK2(val[2 * rp], val[2 * rp + 1], acc[rp]);
        g_Wht[(n0 + 2 * rp + 0) * COLS + c] = val[2 * rp];
        g_Wht[(n0 + 2 * rp + 1) * COLS + c] = val[2 * rp + 1];
    }
    uint32_t hp[8];
#pragma unroll
    for (int q = 0; q < 8; q++) CVT_F16X2(hp[q], val[2 * q], val[2 * q + 1]);
    uint4* pd = (uint4*)(g_WTf16 + (size_t)c * NN + n0);
    pd[0] = make_uint4(hp[0], hp[1], hp[2], hp[3]);
    pd[1] = make_uint4(hp[4], hp[5], hp[6], hp[7]);
}

// ---------------------------------------------------------------------------
// Kernel 1b: scores + exp precompute (fp16 E/F)
// ---------------------------------------------------------------------------
__global__ __launch_bounds__(256) void k_scores(const float* __restrict__ a)
{
    const int gw   = (blockIdx.x * blockDim.x + threadIdx.x) >> 5;
    const int lane = threadIdx.x & 31;
    const int n = gw >> 2, head = gw & 3;

    float2 wv = *(const float2*)(g_Wht + n * COLS + head * HDIM + lane * 2);
    float a1x = a[lane * 2],      a1y = a[lane * 2 + 1];
    float a2x = a[64 + lane * 2], a2y = a[64 + lane * 2 + 1];
    float p1 = wv.x * a1x + wv.y * a1y;
    float p2 = wv.x * a2x + wv.y * a2y;
#pragma unroll
    for (int off = 16; off > 0; off >>= 1) {
        p1 += __shfl_xor_sync(0xFFFFFFFFu, p1, off);
        p2 += __shfl_xor_sync(0xFFFFFFFFu, p2, off);
    }
    if (lane == 0) {
        __half e1 = __float2half(expf(p1));
        __half f1 = __float2half(expf(0.2f * p1));
        uint32_t e1b, f1b;
        memcpy(&e1b, &e1, 2); e1b &= 0xFFFFu;
        memcpy(&f1b, &f1, 2); f1b &= 0xFFFFu;
        g_S16[n * NHEAD + head] = e1b | (f1b << 16);
        g_E2h[head * NN + n] = __float2half(expf(p2));
        g_F2h[head * NN + n] = __float2half(expf(0.2f * p2));
    }
}

// ---------------------------------------------------------------------------
// Kernel 2: HMMA attention aggregation. grid = (NN/TI)*JS = 1024, 256 thr,
// 2 blocks/SM. Warp = 32 rows x 1 head. fp16-native weight phase:
// w = max.f16x2(E1*E2, F1*F2) & prmt-expanded adj mask; den via ones-MMA.
// ---------------------------------------------------------------------------
__global__ __launch_bounds__(256, 2) void k_attn()
{
    extern __shared__ __align__(16) char dsm[];
    const uint32_t sb = smem_u32(dsm);
    const uint32_t ab = (sb + 1023u) & ~1023u;
    char* abp = dsm + (ab - sb);

    const int t    = threadIdx.x;
    const int wid  = t >> 5;
    const int lane = t & 31;
    const int g    = lane >> 2;
    const int tg   = lane & 3;
    const int rg   = wid >> 2;         // rowgroup 0..1 (32 rows each)
    const int h    = wid & 3;          // head
    const int bx = blockIdx.x;
    const int js    = bx & (JS - 1);
    const int itile = bx >> 3;         // JS = 8
    const int i0     = itile * TI;
    const int j0base = js * (NN / JS);

    const int rbase = i0 + rg * 32 + g;    // rows rbase + {0,8,16,24}
    const uint32_t ONES2 = 0x3C003C00u;

    // per-row {E1,E1} / {F1,F1} f16x2 + spread-adj base ptrs
    uint32_t s1E[4], s1F[4];
    const uint32_t* ap[4];
#pragma unroll
    for (int ri = 0; ri < 4; ri++) {
        const int row = rbase + ri * 8;
        uint32_t sv = g_S16[row * NHEAD + h];
        PRMT(s1E[ri], sv, 0x1010);    // {E1, E1}
        PRMT(s1F[ri], sv, 0x3232);    // {F1, F1}
        ap[ri] = g_adjS + ((size_t)row * 128 + (j0base >> 6)) * 4 + tg;
    }

    auto stage = [&](int buf, int j0) {
#pragma unroll
        for (int v = 0; v < 8; v++) {
            int idx = v * 256 + t;
            int row = idx >> 3, u = idx & 7;
            const __half* src = g_WTf16 + (size_t)row * NN + j0 + u * 8;
            uint32_t dst = ab + OFF_B + buf * 32768 + SMEM_SWZ((uint32_t)(row * 128 + u * 16));
            CP_ASYNC16(dst, src);
        }
        if (t < 64) {
            int hh = t >> 4, plane = (t >> 3) & 1, gn = t & 7;
            const __half* src = (plane ? g_F2h : g_E2h) + (size_t)hh * NN + j0 + gn * 8;
            uint32_t dst = ab + OFF_EFS + buf * 1024 + (uint32_t)(hh * 256 + plane * 128 + gn * 16);
            CP_ASYNC16(dst, src);
        }
    };

    stage(0, j0base);
    CP_COMMIT();
    stage(1, j0base + TJ);
    CP_COMMIT();

    float acc[2][8][4];
#pragma unroll
    for (int mt = 0; mt < 2; mt++)
#pragma unroll
        for (int nt = 0; nt < 8; nt++)
#pragma unroll
            for (int q = 0; q < 4; q++) acc[mt][nt][q] = 0.0f;
    float accd[2][4];
#pragma unroll
    for (int mt = 0; mt < 2; mt++)
#pragma unroll
        for (int q = 0; q < 4; q++) accd[mt][q] = 0.0f;

    for (int ch = 0; ch < JCH; ch++) {
        const int buf = ch % 3;
        const int j0  = j0base + ch * TJ;

        // spread adj words for this chunk (4 rows, L2-resident, read once)
        uint32_t aw[4];
#pragma unroll
        for (int ri = 0; ri < 4; ri++) aw[ri] = ap[ri][ch * 4];

        if (ch < JCH - 1) CP_WAIT(1); else CP_WAIT(0);
        __syncthreads();

        if (ch + 2 < JCH) {
            stage((ch + 2) % 3, j0 + 2 * TJ);
            CP_COMMIT();
        }

        const uint32_t Eoff = OFF_EFS + buf * 1024 + (uint32_t)h * 256;
        const uint32_t Bb = ab + OFF_B + buf * 32768;
        const int r_c = lane & 7;
        const int jo2 = ((lane >> 3) & 1) * 8;

#pragma unroll
        for (int sp = 0; sp < 2; sp++) {
#pragma unroll
            for (int k2 = 0; k2 < 2; k2++) {
                const int s = sp * 2 + k2;
                const uint32_t eb = Eoff + (uint32_t)(s * 8 + tg) * 4;
                uint32_t e01 = *(const uint32_t*)(abp + eb);
                uint32_t e89 = *(const uint32_t*)(abp + eb + 16);
                uint32_t f01 = *(const uint32_t*)(abp + eb + 128);
                uint32_t f89 = *(const uint32_t*)(abp + eb + 144);

                uint32_t amt[2][4];
#pragma unroll
                for (int ri = 0; ri < 4; ri++) {
                    uint32_t xs = aw[ri] << (3 - s);
                    uint32_t m01, m89;
                    PRMT(m01, xs, 0x9988);
                    PRMT(m89, xs, 0xBBAA);
                    uint32_t t1, t2, w01, w89;
                    HMUL2(t1, s1E[ri], e01);
                    HMUL2(t2, s1F[ri], f01);
                    HMAX2(w01, t1, t2);
                    HMUL2(t1, s1E[ri], e89);
                    HMUL2(t2, s1F[ri], f89);
                    HMAX2(w89, t1, t2);
                    amt[ri >> 1][ri & 1]       = w01 & m01;
                    amt[ri >> 1][(ri & 1) + 2] = w89 & m89;
                }

                // denominator: ones-B MMA per m-tile (row sums of masked w)
                MMA16816(accd[0], amt[0][0], amt[0][1], amt[0][2], amt[0][3], ONES2, ONES2);
                MMA16816(accd[1], amt[1][0], amt[1][1], amt[1][2], amt[1][3], ONES2, ONES2);

                // B fragments (x2 per n-tile) + MMAs, 2 quads of 4 n-tiles
#pragma unroll
                for (int ntq = 0; ntq < 2; ntq++) {
                    uint32_t bfr[4][2];
#pragma unroll
                    for (int q = 0; q < 4; q++) {
                        int nt = ntq * 4 + q;
                        uint32_t addr = Bb + (uint32_t)(h * 8192)
                            + SMEM_SWZ((uint32_t)((nt * 8 + r_c) * 128
                                                  + (sp * 32 + k2 * 16 + jo2) * 2));
                        LDSM2(bfr[q][0], bfr[q][1], addr);
                    }
#pragma unroll
                    for (int mt = 0; mt < 2; mt++)
#pragma unroll
                        for (int q = 0; q < 4; q++)
                            MMA16816(acc[mt][ntq * 4 + q],
                                     amt[mt][0], amt[mt][1], amt[mt][2], amt[mt][3],
                                     bfr[q][0], bfr[q][1]);
                }
            }
        }
    }

    // ---- epilogue ----
    if (tg == 0) {
#pragma unroll
        for (int ri = 0; ri < 4; ri++)
            g_denP[((size_t)js * NN + rbase + ri * 8) * NHEAD + h] =
                accd[ri >> 1][(ri & 1) * 2];
    }
#pragma unroll
    for (int mt = 0; mt < 2; mt++) {
        const size_t r0 = (size_t)js * NN + rbase + mt * 16;
#pragma unroll
        for (int nt = 0; nt < 8; nt++) {
            const int c0 = h * 64 + nt * 8 + tg * 2;
            *(float2*)(g_outP + r0 * COLS + c0) =
                make_float2(acc[mt][nt][0], acc[mt][nt][1]);
            *(float2*)(g_outP + (r0 + 8) * COLS + c0) =
                make_float2(acc[mt][nt][2], acc[mt][nt][3]);
        }
    }
}

// ---------------------------------------------------------------------------
// Kernel 3: combine j-split partials
// ---------------------------------------------------------------------------
__global__ __launch_bounds__(256) void k_comb(float* __restrict__ out)
{
    const int idx = blockIdx.x * 256 + threadIdx.x;   // float4 index over NN*64
    const int i  = idx >> 6;
    const int c4 = idx & 63;
    const int h  = c4 >> 4;

    float4 s = make_float4(0.f, 0.f, 0.f, 0.f);
    float d = 0.f;
#pragma unroll
    for (int js = 0; js < JS; js++) {
        float4 p = ((const float4*)g_outP)[((size_t)js * NN + i) * 64 + c4];
        s.x += p.x; s.y += p.y; s.z += p.z; s.w += p.w;
        d += g_denP[((size_t)js * NN + i) * NHEAD + h];
    }
    float inv = 1.0f / d;
    ((float4*)out)[idx] = make_float4(s.x * inv, s.y * inv, s.z * inv, s.w * inv);
}

// ---------------------------------------------------------------------------
extern "C" void kernel_launch(void* const* d_in, const int* in_sizes, int n_in,
                              void* d_out, int out_size)
{
    const float* hmat = (const float*)d_in[0];   // [8192, 256] f32
    const int*   adj  = (const int*)  d_in[1];   // [8192, 8192] i32
    const float* W    = (const float*)d_in[2];   // [4, 256, 64] f32
    const float* a    = (const float*)d_in[3];   // [128, 1] f32
    float* out = (float*)d_out;                  // [8192, 256] f32

    cudaFuncSetAttribute(k_attn, cudaFuncAttributeMaxDynamicSharedMemorySize, SMEM_REQ);

    k_pack  <<<NN / 8, 256>>>(adj);
    k_gemm  <<<NN / 16, 256>>>(hmat, W);
    k_scores<<<(NN * NHEAD) / 8, 256>>>(a);
    k_attn  <<<(NN / TI) * JS, 256, SMEM_REQ>>>();
    k_comb  <<<(NN * 64) / 256, 256>>>(out);
}